// round 1
// baseline (speedup 1.0000x reference)
#include <cuda_runtime.h>
#include <math.h>

// ---------------------------------------------------------------------------
// TransformerBlock: B=4, T=2048, C=1024, NH=16, HD=64, FF=4096, fp32.
// Round 0: correct fp32 baseline.
//   ln1 -> qkv gemm -> causal flash attention -> proj gemm (+x residual)
//   -> ln2 -> fc gemm (+gelu) -> proj gemm (+residual) -> out
// ---------------------------------------------------------------------------

#define Bsz   4
#define Tlen  2048
#define Cdim  1024
#define NHead 16
#define HDim  64
#define FFdim 4096
#define Mrows (Bsz * Tlen)   // 8192

// ------------------------- scratch (device globals) ------------------------
__device__ float g_H  [Mrows * Cdim];    // ln output (reused for ln2)
__device__ float g_QKV[Mrows * 3 * Cdim];
__device__ float g_ATT[Mrows * Cdim];
__device__ float g_X1 [Mrows * Cdim];
__device__ float g_FF [Mrows * FFdim];

// ------------------------------- LayerNorm ---------------------------------
__global__ void __launch_bounds__(256)
ln_kernel(const float* __restrict__ X, const float* __restrict__ g,
          const float* __restrict__ b, float* __restrict__ Y)
{
    int row = blockIdx.x;
    int tid = threadIdx.x;
    const float4* xr = reinterpret_cast<const float4*>(X + (size_t)row * Cdim);
    float4 v = xr[tid];                        // 256 threads * 4 = 1024
    float sum = v.x + v.y + v.z + v.w;
    float sq  = v.x*v.x + v.y*v.y + v.z*v.z + v.w*v.w;

    __shared__ float s1[256], s2[256];
    s1[tid] = sum; s2[tid] = sq;
    __syncthreads();
    for (int st = 128; st > 0; st >>= 1) {
        if (tid < st) { s1[tid] += s1[tid + st]; s2[tid] += s2[tid + st]; }
        __syncthreads();
    }
    float mu   = s1[0] * (1.0f / Cdim);
    float var  = s2[0] * (1.0f / Cdim) - mu * mu;
    float rstd = rsqrtf(var + 1e-5f);

    const float4 gg = reinterpret_cast<const float4*>(g)[tid];
    const float4 bb = reinterpret_cast<const float4*>(b)[tid];
    float4 o;
    o.x = (v.x - mu) * rstd * gg.x + bb.x;
    o.y = (v.y - mu) * rstd * gg.y + bb.y;
    o.z = (v.z - mu) * rstd * gg.z + bb.z;
    o.w = (v.w - mu) * rstd * gg.w + bb.w;
    reinterpret_cast<float4*>(Y + (size_t)row * Cdim)[tid] = o;
}

// --------------------------------- SGEMM -----------------------------------
// C[M,N] = A[M,K] @ W[K,N] + bias[N]   (epi: 0=none, 1=gelu, 2=+R residual)
// BM=BN=128, BK=16, 256 threads, 8x8 per thread. M%128==N%128==K%16==0.
__device__ __forceinline__ float gelu_f(float x)
{
    float x3 = x * x * x;
    float t  = tanhf(0.7978845608028654f * (x + 0.044715f * x3));
    return 0.5f * x * (1.0f + t);
}

__global__ void __launch_bounds__(256)
sgemm_kernel(const float* __restrict__ A, const float* __restrict__ W,
             const float* __restrict__ bias, const float* __restrict__ R,
             float* __restrict__ C, int M, int N, int K, int epi)
{
    const int BM = 128, BN = 128, BK = 16;
    __shared__ float As[BK * BM];   // As[k*BM + m]  (A stored transposed)
    __shared__ float Bs[BK * BN];   // Bs[k*BN + n]

    int tid = threadIdx.x;
    int tx  = tid & 15;             // 0..15 -> 8 cols each
    int ty  = tid >> 4;             // 0..15 -> 8 rows each
    int m0  = blockIdx.y * BM;
    int n0  = blockIdx.x * BN;

    float acc[8][8];
#pragma unroll
    for (int i = 0; i < 8; i++)
#pragma unroll
        for (int j = 0; j < 8; j++) acc[i][j] = 0.0f;

    for (int k0 = 0; k0 < K; k0 += BK) {
        // load A tile (128x16) transposed into As
#pragma unroll
        for (int i = 0; i < 2; i++) {
            int f  = tid + i * 256;      // 0..511 float4s
            int r  = f >> 2;             // row in tile 0..127
            int c4 = f & 3;              // float4 within the 16-wide k slice
            float4 a = *reinterpret_cast<const float4*>(
                A + (size_t)(m0 + r) * K + k0 + c4 * 4);
            As[(c4 * 4 + 0) * BM + r] = a.x;
            As[(c4 * 4 + 1) * BM + r] = a.y;
            As[(c4 * 4 + 2) * BM + r] = a.z;
            As[(c4 * 4 + 3) * BM + r] = a.w;
            // load B tile (16x128)
            int rb = f >> 5;             // k row 0..15
            int j4 = f & 31;             // float4 col 0..31
            *reinterpret_cast<float4*>(Bs + rb * BN + j4 * 4) =
                *reinterpret_cast<const float4*>(
                    W + (size_t)(k0 + rb) * N + n0 + j4 * 4);
        }
        __syncthreads();

#pragma unroll
        for (int k = 0; k < BK; k++) {
            float a[8], b[8];
            float4 a0 = *reinterpret_cast<const float4*>(&As[k * BM + ty * 8]);
            float4 a1 = *reinterpret_cast<const float4*>(&As[k * BM + ty * 8 + 4]);
            float4 b0 = *reinterpret_cast<const float4*>(&Bs[k * BN + tx * 8]);
            float4 b1 = *reinterpret_cast<const float4*>(&Bs[k * BN + tx * 8 + 4]);
            a[0]=a0.x; a[1]=a0.y; a[2]=a0.z; a[3]=a0.w;
            a[4]=a1.x; a[5]=a1.y; a[6]=a1.z; a[7]=a1.w;
            b[0]=b0.x; b[1]=b0.y; b[2]=b0.z; b[3]=b0.w;
            b[4]=b1.x; b[5]=b1.y; b[6]=b1.z; b[7]=b1.w;
#pragma unroll
            for (int i = 0; i < 8; i++)
#pragma unroll
                for (int j = 0; j < 8; j++)
                    acc[i][j] = fmaf(a[i], b[j], acc[i][j]);
        }
        __syncthreads();
    }

    // epilogue
    float4 bi0 = *reinterpret_cast<const float4*>(bias + n0 + tx * 8);
    float4 bi1 = *reinterpret_cast<const float4*>(bias + n0 + tx * 8 + 4);
    float bv[8] = {bi0.x, bi0.y, bi0.z, bi0.w, bi1.x, bi1.y, bi1.z, bi1.w};

#pragma unroll
    for (int ii = 0; ii < 8; ii++) {
        int row = m0 + ty * 8 + ii;
        float* crow = C + (size_t)row * N + n0 + tx * 8;
        float v[8];
#pragma unroll
        for (int j = 0; j < 8; j++) v[j] = acc[ii][j] + bv[j];
        if (epi == 1) {
#pragma unroll
            for (int j = 0; j < 8; j++) v[j] = gelu_f(v[j]);
        } else if (epi == 2) {
            const float* rrow = R + (size_t)row * N + n0 + tx * 8;
            float4 r0 = *reinterpret_cast<const float4*>(rrow);
            float4 r1 = *reinterpret_cast<const float4*>(rrow + 4);
            v[0]+=r0.x; v[1]+=r0.y; v[2]+=r0.z; v[3]+=r0.w;
            v[4]+=r1.x; v[5]+=r1.y; v[6]+=r1.z; v[7]+=r1.w;
        }
        float4 o0 = {v[0], v[1], v[2], v[3]};
        float4 o1 = {v[4], v[5], v[6], v[7]};
        *reinterpret_cast<float4*>(crow)     = o0;
        *reinterpret_cast<float4*>(crow + 4) = o1;
    }
}

// ---------------------------- causal flash attn ----------------------------
// one thread = one query row; 128 q rows per block; KV tiles of 64 in SMEM.
// q/k/v live inside g_QKV: q at col h*64, k at 1024+h*64, v at 2048+h*64.
__global__ void __launch_bounds__(128)
flash_kernel(const float* __restrict__ QKV, float* __restrict__ ATT)
{
    __shared__ float Ks[64 * 64];
    __shared__ float Vs[64 * 64];

    int tid = threadIdx.x;
    int bx  = blockIdx.x;          // q tile (128 rows)
    int bh  = blockIdx.y;          // b*16 + h
    int b   = bh >> 4;
    int h   = bh & 15;
    int t_q = bx * 128 + tid;

    size_t qrow = (size_t)(b * Tlen + t_q) * (3 * Cdim) + h * HDim;
    float q[HDim];
#pragma unroll
    for (int d4 = 0; d4 < 16; d4++) {
        float4 qq = *reinterpret_cast<const float4*>(QKV + qrow + d4 * 4);
        q[4*d4+0] = qq.x * 0.125f;   // 1/sqrt(64)
        q[4*d4+1] = qq.y * 0.125f;
        q[4*d4+2] = qq.z * 0.125f;
        q[4*d4+3] = qq.w * 0.125f;
    }

    float acc[HDim];
#pragma unroll
    for (int d = 0; d < HDim; d++) acc[d] = 0.0f;
    float m_i = -1e30f, l_i = 0.0f;

    int j0_max = bx * 128 + 64;    // last KV tile start (inclusive)
    for (int j0 = 0; j0 <= j0_max; j0 += 64) {
        // cooperative K/V tile load (64 rows x 64 cols)
#pragma unroll
        for (int i = 0; i < 8; i++) {
            int f  = tid + i * 128;
            int j  = f >> 4;
            int d4 = f & 15;
            size_t base = (size_t)(b * Tlen + j0 + j) * (3 * Cdim) + h * HDim + d4 * 4;
            *reinterpret_cast<float4*>(Ks + j * 64 + d4 * 4) =
                *reinterpret_cast<const float4*>(QKV + base + Cdim);
            *reinterpret_cast<float4*>(Vs + j * 64 + d4 * 4) =
                *reinterpret_cast<const float4*>(QKV + base + 2 * Cdim);
        }
        __syncthreads();

        int j_hi = t_q - j0;
        if (j_hi > 63) j_hi = 63;
        for (int j = 0; j <= j_hi; j++) {
            const float4* K4 = reinterpret_cast<const float4*>(Ks + j * 64);
            float s = 0.0f;
#pragma unroll
            for (int d4 = 0; d4 < 16; d4++) {
                float4 kk = K4[d4];
                s = fmaf(q[4*d4+0], kk.x, s);
                s = fmaf(q[4*d4+1], kk.y, s);
                s = fmaf(q[4*d4+2], kk.z, s);
                s = fmaf(q[4*d4+3], kk.w, s);
            }
            float e;
            if (s > m_i) {                 // new max: rescale (amortized rare)
                float r = __expf(m_i - s);
                l_i *= r;
#pragma unroll
                for (int d = 0; d < HDim; d++) acc[d] *= r;
                m_i = s;
                e = 1.0f;
            } else {
                e = __expf(s - m_i);
            }
            l_i += e;
            const float4* V4 = reinterpret_cast<const float4*>(Vs + j * 64);
#pragma unroll
            for (int d4 = 0; d4 < 16; d4++) {
                float4 vv = V4[d4];
                acc[4*d4+0] = fmaf(e, vv.x, acc[4*d4+0]);
                acc[4*d4+1] = fmaf(e, vv.y, acc[4*d4+1]);
                acc[4*d4+2] = fmaf(e, vv.z, acc[4*d4+2]);
                acc[4*d4+3] = fmaf(e, vv.w, acc[4*d4+3]);
            }
        }
        __syncthreads();
    }

    float inv = 1.0f / l_i;
    size_t ob = (size_t)(b * Tlen + t_q) * Cdim + h * HDim;
#pragma unroll
    for (int d4 = 0; d4 < 16; d4++) {
        float4 o;
        o.x = acc[4*d4+0] * inv;
        o.y = acc[4*d4+1] * inv;
        o.z = acc[4*d4+2] * inv;
        o.w = acc[4*d4+3] * inv;
        *reinterpret_cast<float4*>(ATT + ob + d4 * 4) = o;
    }
}

// -------------------------------- launcher ---------------------------------
extern "C" void kernel_launch(void* const* d_in, const int* in_sizes, int n_in,
                              void* d_out, int out_size)
{
    const float* x           = (const float*)d_in[0];
    const float* ln1_g       = (const float*)d_in[1];
    const float* ln1_b       = (const float*)d_in[2];
    const float* w_qkv       = (const float*)d_in[3];
    const float* b_qkv       = (const float*)d_in[4];
    const float* w_attn_proj = (const float*)d_in[5];
    const float* b_attn_proj = (const float*)d_in[6];
    const float* ln2_g       = (const float*)d_in[7];
    const float* ln2_b       = (const float*)d_in[8];
    const float* w_fc        = (const float*)d_in[9];
    const float* b_fc        = (const float*)d_in[10];
    const float* w_mlp_proj  = (const float*)d_in[11];
    const float* b_mlp_proj  = (const float*)d_in[12];
    float* out = (float*)d_out;

    float *H, *QKV, *ATT, *X1, *FF;
    cudaGetSymbolAddress((void**)&H,   g_H);
    cudaGetSymbolAddress((void**)&QKV, g_QKV);
    cudaGetSymbolAddress((void**)&ATT, g_ATT);
    cudaGetSymbolAddress((void**)&X1,  g_X1);
    cudaGetSymbolAddress((void**)&FF,  g_FF);

    // 1. h = LN1(x)
    ln_kernel<<<Mrows, 256>>>(x, ln1_g, ln1_b, H);
    // 2. qkv = h @ w_qkv + b_qkv
    sgemm_kernel<<<dim3(3 * Cdim / 128, Mrows / 128), 256>>>(
        H, w_qkv, b_qkv, nullptr, QKV, Mrows, 3 * Cdim, Cdim, 0);
    // 3. causal attention
    flash_kernel<<<dim3(Tlen / 128, Bsz * NHead), 128>>>(QKV, ATT);
    // 4. x1 = x + attn @ w_attn_proj + b
    sgemm_kernel<<<dim3(Cdim / 128, Mrows / 128), 256>>>(
        ATT, w_attn_proj, b_attn_proj, x, X1, Mrows, Cdim, Cdim, 2);
    // 5. h = LN2(x1)
    ln_kernel<<<Mrows, 256>>>(X1, ln2_g, ln2_b, H);
    // 6. ff = gelu(h @ w_fc + b_fc)
    sgemm_kernel<<<dim3(FFdim / 128, Mrows / 128), 256>>>(
        H, w_fc, b_fc, nullptr, FF, Mrows, FFdim, Cdim, 1);
    // 7. out = x1 + ff @ w_mlp_proj + b
    sgemm_kernel<<<dim3(Cdim / 128, Mrows / 128), 256>>>(
        FF, w_mlp_proj, b_mlp_proj, X1, out, Mrows, Cdim, FFdim, 2);
}

// round 3
// speedup vs baseline: 1.4729x; 1.4729x over previous
#include <cuda_runtime.h>
#include <math.h>
#include <stdint.h>
#include <mma.h>

using namespace nvcuda;

// ---------------------------------------------------------------------------
// TransformerBlock B=4,T=2048,C=1024,NH=16,HD=64,FF=4096 fp32.
// R2: GEMMs via wmma tf32 (m16n16k8, HMMA — baseline PTX, works on sm_103).
//     LN + fp32 flash attention unchanged from the passing R0 kernel.
// ---------------------------------------------------------------------------

#define Bsz   4
#define Tlen  2048
#define Cdim  1024
#define NHead 16
#define HDim  64
#define FFdim 4096
#define Mrows (Bsz * Tlen)   // 8192

// ------------------------- scratch (device globals) ------------------------
__device__ float g_H  [Mrows * Cdim];
__device__ float g_QKV[Mrows * 3 * Cdim];
__device__ float g_ATT[Mrows * Cdim];
__device__ float g_X1 [Mrows * Cdim];
__device__ float g_FF [Mrows * FFdim];

// ------------------------------- LayerNorm ---------------------------------
__global__ void __launch_bounds__(256)
ln_kernel(const float* __restrict__ X, const float* __restrict__ g,
          const float* __restrict__ b, float* __restrict__ Y)
{
    int row = blockIdx.x;
    int tid = threadIdx.x;
    const float4* xr = reinterpret_cast<const float4*>(X + (size_t)row * Cdim);
    float4 v = xr[tid];
    float sum = v.x + v.y + v.z + v.w;
    float sq  = v.x*v.x + v.y*v.y + v.z*v.z + v.w*v.w;

    __shared__ float s1[256], s2[256];
    s1[tid] = sum; s2[tid] = sq;
    __syncthreads();
    for (int st = 128; st > 0; st >>= 1) {
        if (tid < st) { s1[tid] += s1[tid + st]; s2[tid] += s2[tid + st]; }
        __syncthreads();
    }
    float mu   = s1[0] * (1.0f / Cdim);
    float var  = s2[0] * (1.0f / Cdim) - mu * mu;
    float rstd = rsqrtf(var + 1e-5f);

    const float4 gg = reinterpret_cast<const float4*>(g)[tid];
    const float4 bb = reinterpret_cast<const float4*>(b)[tid];
    float4 o;
    o.x = (v.x - mu) * rstd * gg.x + bb.x;
    o.y = (v.y - mu) * rstd * gg.y + bb.y;
    o.z = (v.z - mu) * rstd * gg.z + bb.z;
    o.w = (v.w - mu) * rstd * gg.w + bb.w;
    reinterpret_cast<float4*>(Y + (size_t)row * Cdim)[tid] = o;
}

// --------------------------- wmma tf32 GEMM --------------------------------
// C[M,N] = A[M,K] @ W[K,N] + bias ; EPI: 0 none, 1 gelu, 2 +R residual
__device__ __forceinline__ float gelu_f(float x)
{
    float x3 = x * x * x;
    float t  = tanhf(0.7978845608028654f * (x + 0.044715f * x3));
    return 0.5f * x * (1.0f + t);
}

#define CP_ASYNC16(dst, src) \
    asm volatile("cp.async.cg.shared.global [%0], [%1], 16;" :: "r"(dst), "l"(src))
#define CP_COMMIT()   asm volatile("cp.async.commit_group;" ::: "memory")
#define CP_WAIT(n)    asm volatile("cp.async.wait_group %0;" :: "n"(n) : "memory")

__device__ __forceinline__ uint32_t smem_u32(const void* p) {
    uint32_t a;
    asm("{ .reg .u64 t; cvta.to.shared.u64 t, %1; cvt.u32.u64 %0, t; }"
        : "=r"(a) : "l"(p));
    return a;
}

// tile geometry
static constexpr int BM = 128, BN = 128, BK = 32;
static constexpr int LDA = 36;    // A smem row stride (floats), padded
static constexpr int LDB = 132;   // B smem row stride (floats), padded
static constexpr int A_BYTES = BM * LDA * 4;         // 18432
static constexpr int B_BYTES = BK * LDB * 4;         // 16896
static constexpr int STAGE   = A_BYTES + B_BYTES;    // 35328
static constexpr int GEMM_SMEM = 2 * STAGE;          // 70656 (>= 128*132*4 for epi)

template<int EPI>
__global__ void __launch_bounds__(256)
gemm_wmma(const float* __restrict__ A, const float* __restrict__ W,
          const float* __restrict__ bias, const float* __restrict__ R,
          float* __restrict__ C, int M, int N, int K)
{
    extern __shared__ __align__(128) char smem[];
    float* sA[2] = { (float*)smem, (float*)(smem + STAGE) };
    float* sB[2] = { (float*)(smem + A_BYTES), (float*)(smem + STAGE + A_BYTES) };
    uint32_t sA_u[2] = { smem_u32(sA[0]), smem_u32(sA[1]) };
    uint32_t sB_u[2] = { smem_u32(sB[0]), smem_u32(sB[1]) };

    int tid = threadIdx.x;
    int wid = tid >> 5;
    int wm  = wid >> 2;          // 0..1  (64-row slab)
    int wn  = wid & 3;           // 0..3  (32-col slab)
    int m0  = blockIdx.y * BM;
    int n0  = blockIdx.x * BN;

    wmma::fragment<wmma::accumulator, 16, 16, 8, float> acc[4][2];
#pragma unroll
    for (int i = 0; i < 4; i++)
#pragma unroll
        for (int j = 0; j < 2; j++) wmma::fill_fragment(acc[i][j], 0.0f);

    int nk = K / BK;

    // prefetch stage 0
    {
        const float* Ab = A + (size_t)m0 * K;
        const float* Wb = W + (size_t)0 * N + n0;
#pragma unroll
        for (int i = 0; i < 4; i++) {
            int f = tid + i * 256;
            int ra = f >> 3, ca = f & 7;                 // A: 128 rows x 8 f4
            CP_ASYNC16(sA_u[0] + (ra * LDA + ca * 4) * 4,
                       Ab + (size_t)ra * K + ca * 4);
            int rb = f >> 5, cb = f & 31;                // B: 32 rows x 32 f4
            CP_ASYNC16(sB_u[0] + (rb * LDB + cb * 4) * 4,
                       Wb + (size_t)rb * N + cb * 4);
        }
        CP_COMMIT();
    }

    for (int s = 0; s < nk; ++s) {
        int buf = s & 1;
        if (s + 1 < nk) {
            int nb = buf ^ 1;
            const float* Ab = A + (size_t)m0 * K + (s + 1) * BK;
            const float* Wb = W + (size_t)(s + 1) * BK * N + n0;
#pragma unroll
            for (int i = 0; i < 4; i++) {
                int f = tid + i * 256;
                int ra = f >> 3, ca = f & 7;
                CP_ASYNC16(sA_u[nb] + (ra * LDA + ca * 4) * 4,
                           Ab + (size_t)ra * K + ca * 4);
                int rb = f >> 5, cb = f & 31;
                CP_ASYNC16(sB_u[nb] + (rb * LDB + cb * 4) * 4,
                           Wb + (size_t)rb * N + cb * 4);
            }
            CP_COMMIT();
            CP_WAIT(1);
        } else {
            CP_WAIT(0);
        }
        __syncthreads();

        const float* a_base = sA[buf] + (wm * 64) * LDA;
        const float* b_base = sB[buf] + wn * 32;
#pragma unroll
        for (int ks = 0; ks < 4; ++ks) {
            wmma::fragment<wmma::matrix_a, 16, 16, 8, wmma::precision::tf32,
                           wmma::row_major> fa[4];
            wmma::fragment<wmma::matrix_b, 16, 16, 8, wmma::precision::tf32,
                           wmma::row_major> fb[2];
#pragma unroll
            for (int mi = 0; mi < 4; mi++) {
                wmma::load_matrix_sync(fa[mi], a_base + mi * 16 * LDA + ks * 8, LDA);
#pragma unroll
                for (int e = 0; e < fa[mi].num_elements; e++)
                    fa[mi].x[e] = wmma::__float_to_tf32(fa[mi].x[e]);
            }
#pragma unroll
            for (int ni = 0; ni < 2; ni++) {
                wmma::load_matrix_sync(fb[ni], b_base + ks * 8 * LDB + ni * 16, LDB);
#pragma unroll
                for (int e = 0; e < fb[ni].num_elements; e++)
                    fb[ni].x[e] = wmma::__float_to_tf32(fb[ni].x[e]);
            }
#pragma unroll
            for (int mi = 0; mi < 4; mi++)
#pragma unroll
                for (int ni = 0; ni < 2; ni++)
                    wmma::mma_sync(acc[mi][ni], fa[mi], fb[ni], acc[mi][ni]);
        }
        __syncthreads();
    }

    // ---- epilogue: acc -> smem -> fused bias/gelu/residual -> C ----
    float* sC = (float*)smem;     // 128 x LDB(132)
#pragma unroll
    for (int mi = 0; mi < 4; mi++)
#pragma unroll
        for (int ni = 0; ni < 2; ni++)
            wmma::store_matrix_sync(
                sC + (wm * 64 + mi * 16) * LDB + wn * 32 + ni * 16,
                acc[mi][ni], LDB, wmma::mem_row_major);
    __syncthreads();

    int row  = tid >> 1;                 // 0..127
    int cb0  = (tid & 1) * 64;           // 0 or 64
    int grow = m0 + row;
    float* crow = C + (size_t)grow * N + n0 + cb0;
    const float* rrow = (EPI == 2) ? (R + (size_t)grow * N + n0 + cb0) : nullptr;
    const float* srow = sC + row * LDB + cb0;
    const float* brow = bias + n0 + cb0;
#pragma unroll
    for (int j4 = 0; j4 < 16; ++j4) {
        float4 v = *reinterpret_cast<const float4*>(srow + j4 * 4);
        float4 bi = *reinterpret_cast<const float4*>(brow + j4 * 4);
        v.x += bi.x; v.y += bi.y; v.z += bi.z; v.w += bi.w;
        if (EPI == 1) {
            v.x = gelu_f(v.x); v.y = gelu_f(v.y);
            v.z = gelu_f(v.z); v.w = gelu_f(v.w);
        } else if (EPI == 2) {
            float4 r = *reinterpret_cast<const float4*>(rrow + j4 * 4);
            v.x += r.x; v.y += r.y; v.z += r.z; v.w += r.w;
        }
        *reinterpret_cast<float4*>(crow + j4 * 4) = v;
    }
}

// ---------------------------- causal flash attn ----------------------------
__global__ void __launch_bounds__(128)
flash_kernel(const float* __restrict__ QKV, float* __restrict__ ATT)
{
    __shared__ float Ks[64 * 64];
    __shared__ float Vs[64 * 64];

    int tid = threadIdx.x;
    int bx  = blockIdx.x;
    int bh  = blockIdx.y;
    int b   = bh >> 4;
    int h   = bh & 15;
    int t_q = bx * 128 + tid;

    size_t qrow = (size_t)(b * Tlen + t_q) * (3 * Cdim) + h * HDim;
    float q[HDim];
#pragma unroll
    for (int d4 = 0; d4 < 16; d4++) {
        float4 qq = *reinterpret_cast<const float4*>(QKV + qrow + d4 * 4);
        q[4*d4+0] = qq.x * 0.125f;
        q[4*d4+1] = qq.y * 0.125f;
        q[4*d4+2] = qq.z * 0.125f;
        q[4*d4+3] = qq.w * 0.125f;
    }

    float acc[HDim];
#pragma unroll
    for (int d = 0; d < HDim; d++) acc[d] = 0.0f;
    float m_i = -1e30f, l_i = 0.0f;

    int j0_max = bx * 128 + 64;
    for (int j0 = 0; j0 <= j0_max; j0 += 64) {
#pragma unroll
        for (int i = 0; i < 8; i++) {
            int f  = tid + i * 128;
            int j  = f >> 4;
            int d4 = f & 15;
            size_t base = (size_t)(b * Tlen + j0 + j) * (3 * Cdim) + h * HDim + d4 * 4;
            *reinterpret_cast<float4*>(Ks + j * 64 + d4 * 4) =
                *reinterpret_cast<const float4*>(QKV + base + Cdim);
            *reinterpret_cast<float4*>(Vs + j * 64 + d4 * 4) =
                *reinterpret_cast<const float4*>(QKV + base + 2 * Cdim);
        }
        __syncthreads();

        int j_hi = t_q - j0;
        if (j_hi > 63) j_hi = 63;
        for (int j = 0; j <= j_hi; j++) {
            const float4* K4 = reinterpret_cast<const float4*>(Ks + j * 64);
            float s = 0.0f;
#pragma unroll
            for (int d4 = 0; d4 < 16; d4++) {
                float4 kk = K4[d4];
                s = fmaf(q[4*d4+0], kk.x, s);
                s = fmaf(q[4*d4+1], kk.y, s);
                s = fmaf(q[4*d4+2], kk.z, s);
                s = fmaf(q[4*d4+3], kk.w, s);
            }
            float e;
            if (s > m_i) {
                float r = __expf(m_i - s);
                l_i *= r;
#pragma unroll
                for (int d = 0; d < HDim; d++) acc[d] *= r;
                m_i = s;
                e = 1.0f;
            } else {
                e = __expf(s - m_i);
            }
            l_i += e;
            const float4* V4 = reinterpret_cast<const float4*>(Vs + j * 64);
#pragma unroll
            for (int d4 = 0; d4 < 16; d4++) {
                float4 vv = V4[d4];
                acc[4*d4+0] = fmaf(e, vv.x, acc[4*d4+0]);
                acc[4*d4+1] = fmaf(e, vv.y, acc[4*d4+1]);
                acc[4*d4+2] = fmaf(e, vv.z, acc[4*d4+2]);
                acc[4*d4+3] = fmaf(e, vv.w, acc[4*d4+3]);
            }
        }
        __syncthreads();
    }

    float inv = 1.0f / l_i;
    size_t ob = (size_t)(b * Tlen + t_q) * Cdim + h * HDim;
#pragma unroll
    for (int d4 = 0; d4 < 16; d4++) {
        float4 o;
        o.x = acc[4*d4+0] * inv;
        o.y = acc[4*d4+1] * inv;
        o.z = acc[4*d4+2] * inv;
        o.w = acc[4*d4+3] * inv;
        *reinterpret_cast<float4*>(ATT + ob + d4 * 4) = o;
    }
}

// -------------------------------- launcher ---------------------------------
extern "C" void kernel_launch(void* const* d_in, const int* in_sizes, int n_in,
                              void* d_out, int out_size)
{
    const float* x           = (const float*)d_in[0];
    const float* ln1_g       = (const float*)d_in[1];
    const float* ln1_b       = (const float*)d_in[2];
    const float* w_qkv       = (const float*)d_in[3];
    const float* b_qkv       = (const float*)d_in[4];
    const float* w_attn_proj = (const float*)d_in[5];
    const float* b_attn_proj = (const float*)d_in[6];
    const float* ln2_g       = (const float*)d_in[7];
    const float* ln2_b       = (const float*)d_in[8];
    const float* w_fc        = (const float*)d_in[9];
    const float* b_fc        = (const float*)d_in[10];
    const float* w_mlp_proj  = (const float*)d_in[11];
    const float* b_mlp_proj  = (const float*)d_in[12];
    float* out = (float*)d_out;

    float *H, *QKV, *ATT, *X1, *FF;
    cudaGetSymbolAddress((void**)&H,   g_H);
    cudaGetSymbolAddress((void**)&QKV, g_QKV);
    cudaGetSymbolAddress((void**)&ATT, g_ATT);
    cudaGetSymbolAddress((void**)&X1,  g_X1);
    cudaGetSymbolAddress((void**)&FF,  g_FF);

    cudaFuncSetAttribute(gemm_wmma<0>, cudaFuncAttributeMaxDynamicSharedMemorySize, GEMM_SMEM);
    cudaFuncSetAttribute(gemm_wmma<1>, cudaFuncAttributeMaxDynamicSharedMemorySize, GEMM_SMEM);
    cudaFuncSetAttribute(gemm_wmma<2>, cudaFuncAttributeMaxDynamicSharedMemorySize, GEMM_SMEM);

    // 1. h = LN1(x)
    ln_kernel<<<Mrows, 256>>>(x, ln1_g, ln1_b, H);
    // 2. qkv = h @ w_qkv + b_qkv
    gemm_wmma<0><<<dim3(3 * Cdim / BN, Mrows / BM), 256, GEMM_SMEM>>>(
        H, w_qkv, b_qkv, nullptr, QKV, Mrows, 3 * Cdim, Cdim);
    // 3. causal attention
    flash_kernel<<<dim3(Tlen / 128, Bsz * NHead), 128>>>(QKV, ATT);
    // 4. x1 = x + attn @ w_attn_proj + b
    gemm_wmma<2><<<dim3(Cdim / BN, Mrows / BM), 256, GEMM_SMEM>>>(
        ATT, w_attn_proj, b_attn_proj, x, X1, Mrows, Cdim, Cdim);
    // 5. h = LN2(x1)
    ln_kernel<<<Mrows, 256>>>(X1, ln2_g, ln2_b, H);
    // 6. ff = gelu(h @ w_fc + b_fc)
    gemm_wmma<1><<<dim3(FFdim / BN, Mrows / BM), 256, GEMM_SMEM>>>(
        H, w_fc, b_fc, nullptr, FF, Mrows, FFdim, Cdim);
    // 7. out = x1 + ff @ w_mlp_proj + b
    gemm_wmma<2><<<dim3(Cdim / BN, Mrows / BM), 256, GEMM_SMEM>>>(
        FF, w_mlp_proj, b_mlp_proj, X1, out, Mrows, Cdim, FFdim);
}

// round 4
// speedup vs baseline: 2.6315x; 1.7866x over previous
#include <cuda_runtime.h>
#include <cuda_fp16.h>
#include <math.h>
#include <stdint.h>
#include <mma.h>

using namespace nvcuda;

// ---------------------------------------------------------------------------
// TransformerBlock B=4,T=2048,C=1024,NH=16,HD=64,FF=4096 fp32.
// R3: GEMMs via wmma fp16 m16n16k16 (fp32 accum), fp16 activations/weights,
//     2 CTAs/SM. LN/attention math stays fp32.
// ---------------------------------------------------------------------------

#define Bsz   4
#define Tlen  2048
#define Cdim  1024
#define NHead 16
#define HDim  64
#define FFdim 4096
#define Mrows (Bsz * Tlen)   // 8192

// ------------------------- scratch (device globals) ------------------------
__device__ float  g_QKV[Mrows * 3 * Cdim];
__device__ float  g_X1 [Mrows * Cdim];
__device__ __half g_H16 [Mrows * Cdim];
__device__ __half g_ATT16[Mrows * Cdim];
__device__ __half g_FF16 [Mrows * FFdim];
__device__ __half g_Wq16[Cdim * 3 * Cdim];
__device__ __half g_Wa16[Cdim * Cdim];
__device__ __half g_Wf16[Cdim * FFdim];
__device__ __half g_Wm16[FFdim * Cdim];

// --------------------------- fp32 -> fp16 convert --------------------------
__global__ void __launch_bounds__(256)
cvt_half_kernel(const float* __restrict__ in, __half* __restrict__ out, int n4)
{
    int i = blockIdx.x * 256 + threadIdx.x;
    if (i < n4) {
        float4 v = reinterpret_cast<const float4*>(in)[i];
        __half2 h0 = __floats2half2_rn(v.x, v.y);
        __half2 h1 = __floats2half2_rn(v.z, v.w);
        uint2 o = { *(uint32_t*)&h0, *(uint32_t*)&h1 };
        reinterpret_cast<uint2*>(out)[i] = o;
    }
}

// ------------------------------- LayerNorm ---------------------------------
// fp32 in, fp16 out
__global__ void __launch_bounds__(256)
ln_kernel(const float* __restrict__ X, const float* __restrict__ g,
          const float* __restrict__ b, __half* __restrict__ Y)
{
    int row = blockIdx.x;
    int tid = threadIdx.x;
    const float4* xr = reinterpret_cast<const float4*>(X + (size_t)row * Cdim);
    float4 v = xr[tid];
    float sum = v.x + v.y + v.z + v.w;
    float sq  = v.x*v.x + v.y*v.y + v.z*v.z + v.w*v.w;

    __shared__ float s1[256], s2[256];
    s1[tid] = sum; s2[tid] = sq;
    __syncthreads();
    for (int st = 128; st > 0; st >>= 1) {
        if (tid < st) { s1[tid] += s1[tid + st]; s2[tid] += s2[tid + st]; }
        __syncthreads();
    }
    float mu   = s1[0] * (1.0f / Cdim);
    float var  = s2[0] * (1.0f / Cdim) - mu * mu;
    float rstd = rsqrtf(var + 1e-5f);

    const float4 gg = reinterpret_cast<const float4*>(g)[tid];
    const float4 bb = reinterpret_cast<const float4*>(b)[tid];
    __half2 h0 = __floats2half2_rn((v.x - mu) * rstd * gg.x + bb.x,
                                   (v.y - mu) * rstd * gg.y + bb.y);
    __half2 h1 = __floats2half2_rn((v.z - mu) * rstd * gg.z + bb.z,
                                   (v.w - mu) * rstd * gg.w + bb.w);
    uint2 o = { *(uint32_t*)&h0, *(uint32_t*)&h1 };
    reinterpret_cast<uint2*>(Y + (size_t)row * Cdim)[tid] = o;
}

// ----------------------------- fp16 wmma GEMM ------------------------------
__device__ __forceinline__ float gelu_f(float x)
{
    float x3 = x * x * x;
    float t  = tanhf(0.7978845608028654f * (x + 0.044715f * x3));
    return 0.5f * x * (1.0f + t);
}

#define CP_ASYNC16(dst, src) \
    asm volatile("cp.async.cg.shared.global [%0], [%1], 16;" :: "r"(dst), "l"(src))
#define CP_COMMIT()   asm volatile("cp.async.commit_group;" ::: "memory")
#define CP_WAIT(n)    asm volatile("cp.async.wait_group %0;" :: "n"(n) : "memory")

__device__ __forceinline__ uint32_t smem_u32(const void* p) {
    uint32_t a;
    asm("{ .reg .u64 t; cvta.to.shared.u64 t, %1; cvt.u32.u64 %0, t; }"
        : "=r"(a) : "l"(p));
    return a;
}

static constexpr int BM = 128, BN = 128, BK = 32;
static constexpr int LDA = 56;    // halves; 112B row stride (16B-mult, conflict-free)
static constexpr int LDB = 136;   // halves; 272B row stride
static constexpr int A_BYTES = BM * LDA * 2;       // 14336
static constexpr int B_BYTES = BK * LDB * 2;       // 8704
static constexpr int STAGE   = A_BYTES + B_BYTES;  // 23040
static constexpr int LDC = 132;                    // fp32 epilogue stride
static constexpr int GEMM_SMEM = BM * LDC * 4;     // 67584 (> 2*STAGE)

// EPI: 0 none, 1 gelu, 2 +R residual.  OUTH: 1 -> fp16 output, 0 -> fp32.
template<int EPI, int OUTH>
__global__ void __launch_bounds__(256, 2)
gemm_h(const __half* __restrict__ A, const __half* __restrict__ W,
       const float* __restrict__ bias, const float* __restrict__ R,
       void* __restrict__ Cout, int M, int N, int K)
{
    extern __shared__ __align__(128) char smem[];
    __half* sA[2] = { (__half*)smem, (__half*)(smem + STAGE) };
    __half* sB[2] = { (__half*)(smem + A_BYTES), (__half*)(smem + STAGE + A_BYTES) };
    uint32_t sA_u[2] = { smem_u32(sA[0]), smem_u32(sA[1]) };
    uint32_t sB_u[2] = { smem_u32(sB[0]), smem_u32(sB[1]) };

    int tid = threadIdx.x;
    int wid = tid >> 5;
    int wm  = wid >> 2;          // 0..1
    int wn  = wid & 3;           // 0..3
    int m0  = blockIdx.y * BM;
    int n0  = blockIdx.x * BN;

    wmma::fragment<wmma::accumulator, 16, 16, 16, float> acc[4][2];
#pragma unroll
    for (int i = 0; i < 4; i++)
#pragma unroll
        for (int j = 0; j < 2; j++) wmma::fill_fragment(acc[i][j], 0.0f);

    int nk = K / BK;

    // prefetch stage 0
    {
        const __half* Ab = A + (size_t)m0 * K;
        const __half* Wb = W + n0;
#pragma unroll
        for (int i = 0; i < 2; i++) {
            int f = tid + i * 256;
            int ra = f >> 2, ca = f & 3;                 // A: 128 rows x 4 chunks(8h)
            CP_ASYNC16(sA_u[0] + (ra * LDA + ca * 8) * 2,
                       Ab + (size_t)ra * K + ca * 8);
            int rb = f >> 4, cb = f & 15;                // B: 32 rows x 16 chunks
            CP_ASYNC16(sB_u[0] + (rb * LDB + cb * 8) * 2,
                       Wb + (size_t)rb * N + cb * 8);
        }
        CP_COMMIT();
    }

    for (int s = 0; s < nk; ++s) {
        int buf = s & 1;
        if (s + 1 < nk) {
            int nb = buf ^ 1;
            const __half* Ab = A + (size_t)m0 * K + (s + 1) * BK;
            const __half* Wb = W + (size_t)(s + 1) * BK * N + n0;
#pragma unroll
            for (int i = 0; i < 2; i++) {
                int f = tid + i * 256;
                int ra = f >> 2, ca = f & 3;
                CP_ASYNC16(sA_u[nb] + (ra * LDA + ca * 8) * 2,
                           Ab + (size_t)ra * K + ca * 8);
                int rb = f >> 4, cb = f & 15;
                CP_ASYNC16(sB_u[nb] + (rb * LDB + cb * 8) * 2,
                           Wb + (size_t)rb * N + cb * 8);
            }
            CP_COMMIT();
            CP_WAIT(1);
        } else {
            CP_WAIT(0);
        }
        __syncthreads();

        const __half* a_base = sA[buf] + (wm * 64) * LDA;
        const __half* b_base = sB[buf] + wn * 32;
#pragma unroll
        for (int ks = 0; ks < 2; ++ks) {
            wmma::fragment<wmma::matrix_a, 16, 16, 16, __half, wmma::row_major> fa[4];
            wmma::fragment<wmma::matrix_b, 16, 16, 16, __half, wmma::row_major> fb[2];
#pragma unroll
            for (int mi = 0; mi < 4; mi++)
                wmma::load_matrix_sync(fa[mi], a_base + mi * 16 * LDA + ks * 16, LDA);
#pragma unroll
            for (int ni = 0; ni < 2; ni++)
                wmma::load_matrix_sync(fb[ni], b_base + ks * 16 * LDB + ni * 16, LDB);
#pragma unroll
            for (int mi = 0; mi < 4; mi++)
#pragma unroll
                for (int ni = 0; ni < 2; ni++)
                    wmma::mma_sync(acc[mi][ni], fa[mi], fb[ni], acc[mi][ni]);
        }
        __syncthreads();
    }

    // ---- epilogue: acc -> smem(fp32) -> fused bias/gelu/residual -> out ----
    float* sC = (float*)smem;
#pragma unroll
    for (int mi = 0; mi < 4; mi++)
#pragma unroll
        for (int ni = 0; ni < 2; ni++)
            wmma::store_matrix_sync(
                sC + (wm * 64 + mi * 16) * LDC + wn * 32 + ni * 16,
                acc[mi][ni], LDC, wmma::mem_row_major);
    __syncthreads();

    int row  = tid >> 1;
    int cb0  = (tid & 1) * 64;
    int grow = m0 + row;
    const float* rrow = (EPI == 2) ? (R + (size_t)grow * N + n0 + cb0) : nullptr;
    const float* srow = sC + row * LDC + cb0;
    const float* brow = bias + n0 + cb0;
    float*  cfrow = (float*)Cout  + (size_t)grow * N + n0 + cb0;
    __half* chrow = (__half*)Cout + (size_t)grow * N + n0 + cb0;
#pragma unroll
    for (int j4 = 0; j4 < 16; ++j4) {
        float4 v  = *reinterpret_cast<const float4*>(srow + j4 * 4);
        float4 bi = *reinterpret_cast<const float4*>(brow + j4 * 4);
        v.x += bi.x; v.y += bi.y; v.z += bi.z; v.w += bi.w;
        if (EPI == 1) {
            v.x = gelu_f(v.x); v.y = gelu_f(v.y);
            v.z = gelu_f(v.z); v.w = gelu_f(v.w);
        } else if (EPI == 2) {
            float4 r = *reinterpret_cast<const float4*>(rrow + j4 * 4);
            v.x += r.x; v.y += r.y; v.z += r.z; v.w += r.w;
        }
        if (OUTH) {
            __half2 h0 = __floats2half2_rn(v.x, v.y);
            __half2 h1 = __floats2half2_rn(v.z, v.w);
            uint2 o = { *(uint32_t*)&h0, *(uint32_t*)&h1 };
            *reinterpret_cast<uint2*>(chrow + j4 * 4) = o;
        } else {
            *reinterpret_cast<float4*>(cfrow + j4 * 4) = v;
        }
    }
}

// ---------------------------- causal flash attn ----------------------------
// fp32 math; writes fp16 output (input to proj GEMM).
__global__ void __launch_bounds__(128)
flash_kernel(const float* __restrict__ QKV, __half* __restrict__ ATT)
{
    __shared__ float Ks[64 * 64];
    __shared__ float Vs[64 * 64];

    int tid = threadIdx.x;
    int bx  = blockIdx.x;
    int bh  = blockIdx.y;
    int b   = bh >> 4;
    int h   = bh & 15;
    int t_q = bx * 128 + tid;

    size_t qrow = (size_t)(b * Tlen + t_q) * (3 * Cdim) + h * HDim;
    float q[HDim];
#pragma unroll
    for (int d4 = 0; d4 < 16; d4++) {
        float4 qq = *reinterpret_cast<const float4*>(QKV + qrow + d4 * 4);
        q[4*d4+0] = qq.x * 0.125f;
        q[4*d4+1] = qq.y * 0.125f;
        q[4*d4+2] = qq.z * 0.125f;
        q[4*d4+3] = qq.w * 0.125f;
    }

    float acc[HDim];
#pragma unroll
    for (int d = 0; d < HDim; d++) acc[d] = 0.0f;
    float m_i = -1e30f, l_i = 0.0f;

    int j0_max = bx * 128 + 64;
    for (int j0 = 0; j0 <= j0_max; j0 += 64) {
#pragma unroll
        for (int i = 0; i < 8; i++) {
            int f  = tid + i * 128;
            int j  = f >> 4;
            int d4 = f & 15;
            size_t base = (size_t)(b * Tlen + j0 + j) * (3 * Cdim) + h * HDim + d4 * 4;
            *reinterpret_cast<float4*>(Ks + j * 64 + d4 * 4) =
                *reinterpret_cast<const float4*>(QKV + base + Cdim);
            *reinterpret_cast<float4*>(Vs + j * 64 + d4 * 4) =
                *reinterpret_cast<const float4*>(QKV + base + 2 * Cdim);
        }
        __syncthreads();

        int j_hi = t_q - j0;
        if (j_hi > 63) j_hi = 63;
        for (int j = 0; j <= j_hi; j++) {
            const float4* K4 = reinterpret_cast<const float4*>(Ks + j * 64);
            float s = 0.0f;
#pragma unroll
            for (int d4 = 0; d4 < 16; d4++) {
                float4 kk = K4[d4];
                s = fmaf(q[4*d4+0], kk.x, s);
                s = fmaf(q[4*d4+1], kk.y, s);
                s = fmaf(q[4*d4+2], kk.z, s);
                s = fmaf(q[4*d4+3], kk.w, s);
            }
            float e;
            if (s > m_i) {
                float r = __expf(m_i - s);
                l_i *= r;
#pragma unroll
                for (int d = 0; d < HDim; d++) acc[d] *= r;
                m_i = s;
                e = 1.0f;
            } else {
                e = __expf(s - m_i);
            }
            l_i += e;
            const float4* V4 = reinterpret_cast<const float4*>(Vs + j * 64);
#pragma unroll
            for (int d4 = 0; d4 < 16; d4++) {
                float4 vv = V4[d4];
                acc[4*d4+0] = fmaf(e, vv.x, acc[4*d4+0]);
                acc[4*d4+1] = fmaf(e, vv.y, acc[4*d4+1]);
                acc[4*d4+2] = fmaf(e, vv.z, acc[4*d4+2]);
                acc[4*d4+3] = fmaf(e, vv.w, acc[4*d4+3]);
            }
        }
        __syncthreads();
    }

    float inv = 1.0f / l_i;
    size_t ob = (size_t)(b * Tlen + t_q) * Cdim + h * HDim;
#pragma unroll
    for (int d4 = 0; d4 < 16; d4++) {
        __half2 h0 = __floats2half2_rn(acc[4*d4+0] * inv, acc[4*d4+1] * inv);
        __half2 h1 = __floats2half2_rn(acc[4*d4+2] * inv, acc[4*d4+3] * inv);
        uint2 o = { *(uint32_t*)&h0, *(uint32_t*)&h1 };
        *reinterpret_cast<uint2*>(ATT + ob + d4 * 4) = o;
    }
}

// -------------------------------- launcher ---------------------------------
extern "C" void kernel_launch(void* const* d_in, const int* in_sizes, int n_in,
                              void* d_out, int out_size)
{
    const float* x           = (const float*)d_in[0];
    const float* ln1_g       = (const float*)d_in[1];
    const float* ln1_b       = (const float*)d_in[2];
    const float* w_qkv       = (const float*)d_in[3];
    const float* b_qkv       = (const float*)d_in[4];
    const float* w_attn_proj = (const float*)d_in[5];
    const float* b_attn_proj = (const float*)d_in[6];
    const float* ln2_g       = (const float*)d_in[7];
    const float* ln2_b       = (const float*)d_in[8];
    const float* w_fc        = (const float*)d_in[9];
    const float* b_fc        = (const float*)d_in[10];
    const float* w_mlp_proj  = (const float*)d_in[11];
    const float* b_mlp_proj  = (const float*)d_in[12];
    float* out = (float*)d_out;

    float *QKV, *X1;
    __half *H16, *ATT16, *FF16, *Wq16, *Wa16, *Wf16, *Wm16;
    cudaGetSymbolAddress((void**)&QKV,  g_QKV);
    cudaGetSymbolAddress((void**)&X1,   g_X1);
    cudaGetSymbolAddress((void**)&H16,  g_H16);
    cudaGetSymbolAddress((void**)&ATT16,g_ATT16);
    cudaGetSymbolAddress((void**)&FF16, g_FF16);
    cudaGetSymbolAddress((void**)&Wq16, g_Wq16);
    cudaGetSymbolAddress((void**)&Wa16, g_Wa16);
    cudaGetSymbolAddress((void**)&Wf16, g_Wf16);
    cudaGetSymbolAddress((void**)&Wm16, g_Wm16);

    cudaFuncSetAttribute(gemm_h<0,0>, cudaFuncAttributeMaxDynamicSharedMemorySize, GEMM_SMEM);
    cudaFuncSetAttribute(gemm_h<1,1>, cudaFuncAttributeMaxDynamicSharedMemorySize, GEMM_SMEM);
    cudaFuncSetAttribute(gemm_h<2,0>, cudaFuncAttributeMaxDynamicSharedMemorySize, GEMM_SMEM);

    // weight conversions fp32 -> fp16
    cvt_half_kernel<<<(3*Cdim*Cdim/4 + 255)/256, 256>>>(w_qkv, Wq16, 3*Cdim*Cdim/4);
    cvt_half_kernel<<<(Cdim*Cdim/4 + 255)/256, 256>>>(w_attn_proj, Wa16, Cdim*Cdim/4);
    cvt_half_kernel<<<(Cdim*FFdim/4 + 255)/256, 256>>>(w_fc, Wf16, Cdim*FFdim/4);
    cvt_half_kernel<<<(FFdim*Cdim/4 + 255)/256, 256>>>(w_mlp_proj, Wm16, FFdim*Cdim/4);

    // 1. h = LN1(x)            (fp16 out)
    ln_kernel<<<Mrows, 256>>>(x, ln1_g, ln1_b, H16);
    // 2. qkv = h @ w_qkv + b   (fp32 out)
    gemm_h<0,0><<<dim3(3 * Cdim / BN, Mrows / BM), 256, GEMM_SMEM>>>(
        H16, Wq16, b_qkv, nullptr, QKV, Mrows, 3 * Cdim, Cdim);
    // 3. causal attention      (fp16 out)
    flash_kernel<<<dim3(Tlen / 128, Bsz * NHead), 128>>>(QKV, ATT16);
    // 4. x1 = x + attn @ w_attn_proj + b   (fp32 out)
    gemm_h<2,0><<<dim3(Cdim / BN, Mrows / BM), 256, GEMM_SMEM>>>(
        ATT16, Wa16, b_attn_proj, x, X1, Mrows, Cdim, Cdim);
    // 5. h = LN2(x1)           (fp16 out)
    ln_kernel<<<Mrows, 256>>>(X1, ln2_g, ln2_b, H16);
    // 6. ff = gelu(h @ w_fc + b)   (fp16 out)
    gemm_h<1,1><<<dim3(FFdim / BN, Mrows / BM), 256, GEMM_SMEM>>>(
        H16, Wf16, b_fc, nullptr, FF16, Mrows, FFdim, Cdim);
    // 7. out = x1 + ff @ w_mlp_proj + b    (fp32 out)
    gemm_h<2,0><<<dim3(Cdim / BN, Mrows / BM), 256, GEMM_SMEM>>>(
        FF16, Wm16, b_mlp_proj, X1, out, Mrows, Cdim, FFdim);
}

// round 5
// speedup vs baseline: 4.8726x; 1.8517x over previous
#include <cuda_runtime.h>
#include <cuda_fp16.h>
#include <math.h>
#include <stdint.h>
#include <mma.h>

using namespace nvcuda;

// ---------------------------------------------------------------------------
// TransformerBlock B=4,T=2048,C=1024,NH=16,HD=64,FF=4096 fp32.
// R4: fp16 wmma GEMMs (unchanged) + fp16 wmma flash attention.
// ---------------------------------------------------------------------------

#define Bsz   4
#define Tlen  2048
#define Cdim  1024
#define NHead 16
#define HDim  64
#define FFdim 4096
#define Mrows (Bsz * Tlen)   // 8192

// ------------------------- scratch (device globals) ------------------------
__device__ float  g_X1 [Mrows * Cdim];
__device__ __half g_H16  [Mrows * Cdim];
__device__ __half g_QKV16[Mrows * 3 * Cdim];
__device__ __half g_ATT16[Mrows * Cdim];
__device__ __half g_FF16 [Mrows * FFdim];
__device__ __half g_Wq16[Cdim * 3 * Cdim];
__device__ __half g_Wa16[Cdim * Cdim];
__device__ __half g_Wf16[Cdim * FFdim];
__device__ __half g_Wm16[FFdim * Cdim];

// --------------------------- fp32 -> fp16 convert --------------------------
__global__ void __launch_bounds__(256)
cvt_half_kernel(const float* __restrict__ in, __half* __restrict__ out, int n4)
{
    int i = blockIdx.x * 256 + threadIdx.x;
    if (i < n4) {
        float4 v = reinterpret_cast<const float4*>(in)[i];
        __half2 h0 = __floats2half2_rn(v.x, v.y);
        __half2 h1 = __floats2half2_rn(v.z, v.w);
        uint2 o = { *(uint32_t*)&h0, *(uint32_t*)&h1 };
        reinterpret_cast<uint2*>(out)[i] = o;
    }
}

// ------------------------------- LayerNorm ---------------------------------
__global__ void __launch_bounds__(256)
ln_kernel(const float* __restrict__ X, const float* __restrict__ g,
          const float* __restrict__ b, __half* __restrict__ Y)
{
    int row = blockIdx.x;
    int tid = threadIdx.x;
    const float4* xr = reinterpret_cast<const float4*>(X + (size_t)row * Cdim);
    float4 v = xr[tid];
    float sum = v.x + v.y + v.z + v.w;
    float sq  = v.x*v.x + v.y*v.y + v.z*v.z + v.w*v.w;

    __shared__ float s1[256], s2[256];
    s1[tid] = sum; s2[tid] = sq;
    __syncthreads();
    for (int st = 128; st > 0; st >>= 1) {
        if (tid < st) { s1[tid] += s1[tid + st]; s2[tid] += s2[tid + st]; }
        __syncthreads();
    }
    float mu   = s1[0] * (1.0f / Cdim);
    float var  = s2[0] * (1.0f / Cdim) - mu * mu;
    float rstd = rsqrtf(var + 1e-5f);

    const float4 gg = reinterpret_cast<const float4*>(g)[tid];
    const float4 bb = reinterpret_cast<const float4*>(b)[tid];
    __half2 h0 = __floats2half2_rn((v.x - mu) * rstd * gg.x + bb.x,
                                   (v.y - mu) * rstd * gg.y + bb.y);
    __half2 h1 = __floats2half2_rn((v.z - mu) * rstd * gg.z + bb.z,
                                   (v.w - mu) * rstd * gg.w + bb.w);
    uint2 o = { *(uint32_t*)&h0, *(uint32_t*)&h1 };
    reinterpret_cast<uint2*>(Y + (size_t)row * Cdim)[tid] = o;
}

// ------------------------------ common helpers -----------------------------
__device__ __forceinline__ float gelu_f(float x)
{
    float x3 = x * x * x;
    float t  = tanhf(0.7978845608028654f * (x + 0.044715f * x3));
    return 0.5f * x * (1.0f + t);
}

#define CP_ASYNC16(dst, src) \
    asm volatile("cp.async.cg.shared.global [%0], [%1], 16;" :: "r"(dst), "l"(src))
#define CP_COMMIT()   asm volatile("cp.async.commit_group;" ::: "memory")
#define CP_WAIT(n)    asm volatile("cp.async.wait_group %0;" :: "n"(n) : "memory")

__device__ __forceinline__ uint32_t smem_u32(const void* p) {
    uint32_t a;
    asm("{ .reg .u64 t; cvta.to.shared.u64 t, %1; cvt.u32.u64 %0, t; }"
        : "=r"(a) : "l"(p));
    return a;
}

// ----------------------------- fp16 wmma GEMM ------------------------------
static constexpr int BM = 128, BN = 128, BK = 32;
static constexpr int LDA = 56;
static constexpr int LDB = 136;
static constexpr int A_BYTES = BM * LDA * 2;
static constexpr int B_BYTES = BK * LDB * 2;
static constexpr int STAGE   = A_BYTES + B_BYTES;
static constexpr int LDC = 132;
static constexpr int GEMM_SMEM = BM * LDC * 4;

// EPI: 0 none, 1 gelu, 2 +R.  OUTH: 1 fp16 out, 0 fp32 out.
template<int EPI, int OUTH>
__global__ void __launch_bounds__(256, 2)
gemm_h(const __half* __restrict__ A, const __half* __restrict__ W,
       const float* __restrict__ bias, const float* __restrict__ R,
       void* __restrict__ Cout, int M, int N, int K)
{
    extern __shared__ __align__(128) char smem[];
    __half* sA[2] = { (__half*)smem, (__half*)(smem + STAGE) };
    __half* sB[2] = { (__half*)(smem + A_BYTES), (__half*)(smem + STAGE + A_BYTES) };
    uint32_t sA_u[2] = { smem_u32(sA[0]), smem_u32(sA[1]) };
    uint32_t sB_u[2] = { smem_u32(sB[0]), smem_u32(sB[1]) };

    int tid = threadIdx.x;
    int wid = tid >> 5;
    int wm  = wid >> 2;
    int wn  = wid & 3;
    int m0  = blockIdx.y * BM;
    int n0  = blockIdx.x * BN;

    wmma::fragment<wmma::accumulator, 16, 16, 16, float> acc[4][2];
#pragma unroll
    for (int i = 0; i < 4; i++)
#pragma unroll
        for (int j = 0; j < 2; j++) wmma::fill_fragment(acc[i][j], 0.0f);

    int nk = K / BK;

    {
        const __half* Ab = A + (size_t)m0 * K;
        const __half* Wb = W + n0;
#pragma unroll
        for (int i = 0; i < 2; i++) {
            int f = tid + i * 256;
            int ra = f >> 2, ca = f & 3;
            CP_ASYNC16(sA_u[0] + (ra * LDA + ca * 8) * 2,
                       Ab + (size_t)ra * K + ca * 8);
            int rb = f >> 4, cb = f & 15;
            CP_ASYNC16(sB_u[0] + (rb * LDB + cb * 8) * 2,
                       Wb + (size_t)rb * N + cb * 8);
        }
        CP_COMMIT();
    }

    for (int s = 0; s < nk; ++s) {
        int buf = s & 1;
        if (s + 1 < nk) {
            int nb = buf ^ 1;
            const __half* Ab = A + (size_t)m0 * K + (s + 1) * BK;
            const __half* Wb = W + (size_t)(s + 1) * BK * N + n0;
#pragma unroll
            for (int i = 0; i < 2; i++) {
                int f = tid + i * 256;
                int ra = f >> 2, ca = f & 3;
                CP_ASYNC16(sA_u[nb] + (ra * LDA + ca * 8) * 2,
                           Ab + (size_t)ra * K + ca * 8);
                int rb = f >> 4, cb = f & 15;
                CP_ASYNC16(sB_u[nb] + (rb * LDB + cb * 8) * 2,
                           Wb + (size_t)rb * N + cb * 8);
            }
            CP_COMMIT();
            CP_WAIT(1);
        } else {
            CP_WAIT(0);
        }
        __syncthreads();

        const __half* a_base = sA[buf] + (wm * 64) * LDA;
        const __half* b_base = sB[buf] + wn * 32;
#pragma unroll
        for (int ks = 0; ks < 2; ++ks) {
            wmma::fragment<wmma::matrix_a, 16, 16, 16, __half, wmma::row_major> fa[4];
            wmma::fragment<wmma::matrix_b, 16, 16, 16, __half, wmma::row_major> fb[2];
#pragma unroll
            for (int mi = 0; mi < 4; mi++)
                wmma::load_matrix_sync(fa[mi], a_base + mi * 16 * LDA + ks * 16, LDA);
#pragma unroll
            for (int ni = 0; ni < 2; ni++)
                wmma::load_matrix_sync(fb[ni], b_base + ks * 16 * LDB + ni * 16, LDB);
#pragma unroll
            for (int mi = 0; mi < 4; mi++)
#pragma unroll
                for (int ni = 0; ni < 2; ni++)
                    wmma::mma_sync(acc[mi][ni], fa[mi], fb[ni], acc[mi][ni]);
        }
        __syncthreads();
    }

    float* sC = (float*)smem;
#pragma unroll
    for (int mi = 0; mi < 4; mi++)
#pragma unroll
        for (int ni = 0; ni < 2; ni++)
            wmma::store_matrix_sync(
                sC + (wm * 64 + mi * 16) * LDC + wn * 32 + ni * 16,
                acc[mi][ni], LDC, wmma::mem_row_major);
    __syncthreads();

    int row  = tid >> 1;
    int cb0  = (tid & 1) * 64;
    int grow = m0 + row;
    const float* rrow = (EPI == 2) ? (R + (size_t)grow * N + n0 + cb0) : nullptr;
    const float* srow = sC + row * LDC + cb0;
    const float* brow = bias + n0 + cb0;
    float*  cfrow = (float*)Cout  + (size_t)grow * N + n0 + cb0;
    __half* chrow = (__half*)Cout + (size_t)grow * N + n0 + cb0;
#pragma unroll
    for (int j4 = 0; j4 < 16; ++j4) {
        float4 v  = *reinterpret_cast<const float4*>(srow + j4 * 4);
        float4 bi = *reinterpret_cast<const float4*>(brow + j4 * 4);
        v.x += bi.x; v.y += bi.y; v.z += bi.z; v.w += bi.w;
        if (EPI == 1) {
            v.x = gelu_f(v.x); v.y = gelu_f(v.y);
            v.z = gelu_f(v.z); v.w = gelu_f(v.w);
        } else if (EPI == 2) {
            float4 r = *reinterpret_cast<const float4*>(rrow + j4 * 4);
            v.x += r.x; v.y += r.y; v.z += r.z; v.w += r.w;
        }
        if (OUTH) {
            __half2 h0 = __floats2half2_rn(v.x, v.y);
            __half2 h1 = __floats2half2_rn(v.z, v.w);
            uint2 o = { *(uint32_t*)&h0, *(uint32_t*)&h1 };
            *reinterpret_cast<uint2*>(chrow + j4 * 4) = o;
        } else {
            *reinterpret_cast<float4*>(cfrow + j4 * 4) = v;
        }
    }
}

// ------------------------- wmma fp16 flash attention -----------------------
// block: 128 threads (4 warps), 64 q rows, one (b,h). KV tiles of 64.
static constexpr int LQ = 72;   // fp16 tile row stride
static constexpr int LS = 68;   // fp32 tile row stride
static constexpr int Q_OFF = 0;
static constexpr int K_OFF = Q_OFF + 64 * LQ * 2;   //  9216
static constexpr int V_OFF = K_OFF + 64 * LQ * 2;   // 18432
static constexpr int P_OFF = V_OFF + 64 * LQ * 2;   // 27648
static constexpr int S_OFF = P_OFF + 64 * LQ * 2;   // 36864
static constexpr int O_OFF = S_OFF + 64 * LS * 4;   // 54272
static constexpr int M_OFF = O_OFF + 64 * LS * 4;   // 71680
static constexpr int L_OFF = M_OFF + 64 * 4;        // 71936
static constexpr int FLASH_SMEM = L_OFF + 64 * 4;   // 72192

__global__ void __launch_bounds__(128)
flash_wmma(const __half* __restrict__ QKV, __half* __restrict__ ATT)
{
    extern __shared__ __align__(128) char smem[];
    __half* Qs = (__half*)(smem + Q_OFF);
    __half* Ks = (__half*)(smem + K_OFF);
    __half* Vs = (__half*)(smem + V_OFF);
    __half* Ps = (__half*)(smem + P_OFF);
    float*  Ss = (float*)(smem + S_OFF);
    float*  Os = (float*)(smem + O_OFF);
    float*  mrow = (float*)(smem + M_OFF);
    float*  lrow = (float*)(smem + L_OFF);
    uint32_t Qu = smem_u32(Qs), Ku = smem_u32(Ks), Vu = smem_u32(Vs);

    int tid  = threadIdx.x;
    int w    = tid >> 5;
    int lane = tid & 31;
    int qt   = gridDim.x - 1 - blockIdx.x;     // heavy tiles first
    int bh   = blockIdx.y;
    int b    = bh >> 4;
    int h    = bh & 15;
    int q0   = qt * 64;

    // init O, m, l
    for (int i = tid; i < 64 * LS; i += 128) Os[i] = 0.0f;
    if (tid < 64) { mrow[tid] = -1e30f; lrow[tid] = 0.0f; }

    // load Q tile (64 x 64 fp16)
    const __half* Qg = QKV + (size_t)(b * Tlen + q0) * (3 * Cdim) + h * HDim;
#pragma unroll
    for (int i = 0; i < 4; i++) {
        int f = tid + i * 128;
        int r = f >> 3, c8 = f & 7;
        CP_ASYNC16(Qu + (r * LQ + c8 * 8) * 2, Qg + (size_t)r * (3 * Cdim) + c8 * 8);
    }
    CP_COMMIT();
    CP_WAIT(0);
    __syncthreads();

    int srow_q = w * 16 + (lane >> 1);      // softmax row this thread owns
    int half   = lane & 1;
    int qrow_g = q0 + srow_q;

    for (int j0 = 0; j0 <= q0; j0 += 64) {
        // ---- load K/V tile ----
        const __half* Kg = QKV + (size_t)(b * Tlen + j0) * (3 * Cdim) + Cdim + h * HDim;
        const __half* Vg = Kg + Cdim;
#pragma unroll
        for (int i = 0; i < 4; i++) {
            int f = tid + i * 128;
            int r = f >> 3, c8 = f & 7;
            CP_ASYNC16(Ku + (r * LQ + c8 * 8) * 2, Kg + (size_t)r * (3 * Cdim) + c8 * 8);
            CP_ASYNC16(Vu + (r * LQ + c8 * 8) * 2, Vg + (size_t)r * (3 * Cdim) + c8 * 8);
        }
        CP_COMMIT();
        CP_WAIT(0);
        __syncthreads();

        // ---- S = Q @ K^T  (each warp: 16 rows x 64 cols) ----
        {
            wmma::fragment<wmma::matrix_a, 16, 16, 16, __half, wmma::row_major> fa[4];
#pragma unroll
            for (int ks = 0; ks < 4; ks++)
                wmma::load_matrix_sync(fa[ks], Qs + (w * 16) * LQ + ks * 16, LQ);
#pragma unroll
            for (int n = 0; n < 4; n++) {
                wmma::fragment<wmma::accumulator, 16, 16, 16, float> accS;
                wmma::fill_fragment(accS, 0.0f);
#pragma unroll
                for (int ks = 0; ks < 4; ks++) {
                    wmma::fragment<wmma::matrix_b, 16, 16, 16, __half, wmma::col_major> fb;
                    wmma::load_matrix_sync(fb, Ks + (n * 16) * LQ + ks * 16, LQ);
                    wmma::mma_sync(accS, fa[ks], fb, accS);
                }
                wmma::store_matrix_sync(Ss + (w * 16) * LS + n * 16, accS, LS,
                                        wmma::mem_row_major);
            }
        }
        __syncthreads();

        // ---- online softmax (2 threads per row, 32 cols each) ----
        {
            float* sr = Ss + srow_q * LS + half * 32;
            bool diag = (j0 == q0);
            float sv[32];
            float tmax = -1e30f;
#pragma unroll
            for (int c = 0; c < 32; c++) {
                float s = sr[c] * 0.125f;
                if (diag && (j0 + half * 32 + c > qrow_g)) s = -1e30f;
                sv[c] = s;
                tmax = fmaxf(tmax, s);
            }
            tmax = fmaxf(tmax, __shfl_xor_sync(0xFFFFFFFFu, tmax, 1));
            float m_old = mrow[srow_q];
            float m_new = fmaxf(m_old, tmax);
            float scale = __expf(m_old - m_new);
            float sum = 0.0f;
            __half* pr = Ps + srow_q * LQ + half * 32;
#pragma unroll
            for (int c = 0; c < 32; c += 2) {
                float p0 = __expf(sv[c]   - m_new);
                float p1 = __expf(sv[c+1] - m_new);
                sum += p0 + p1;
                __half2 hp = __floats2half2_rn(p0, p1);
                *reinterpret_cast<__half2*>(pr + c) = hp;
            }
            sum += __shfl_xor_sync(0xFFFFFFFFu, sum, 1);
            if (half == 0) {
                mrow[srow_q] = m_new;
                lrow[srow_q] = lrow[srow_q] * scale + sum;
            }
            float* orow = Os + srow_q * LS + half * 32;
#pragma unroll
            for (int c = 0; c < 32; c++) orow[c] *= scale;
        }
        __syncthreads();

        // ---- O += P @ V ----
        {
            wmma::fragment<wmma::matrix_a, 16, 16, 16, __half, wmma::row_major> fp[4];
#pragma unroll
            for (int ks = 0; ks < 4; ks++)
                wmma::load_matrix_sync(fp[ks], Ps + (w * 16) * LQ + ks * 16, LQ);
#pragma unroll
            for (int n = 0; n < 4; n++) {
                wmma::fragment<wmma::accumulator, 16, 16, 16, float> accO;
                wmma::load_matrix_sync(accO, Os + (w * 16) * LS + n * 16, LS,
                                       wmma::mem_row_major);
#pragma unroll
                for (int ks = 0; ks < 4; ks++) {
                    wmma::fragment<wmma::matrix_b, 16, 16, 16, __half, wmma::row_major> fv;
                    wmma::load_matrix_sync(fv, Vs + (ks * 16) * LQ + n * 16, LQ);
                    wmma::mma_sync(accO, fp[ks], fv, accO);
                }
                wmma::store_matrix_sync(Os + (w * 16) * LS + n * 16, accO, LS,
                                        wmma::mem_row_major);
            }
        }
        __syncthreads();
    }

    // ---- normalize + write fp16 output ----
    {
        float inv = 1.0f / lrow[srow_q];
        const float* orow = Os + srow_q * LS + half * 32;
        __half* out = ATT + (size_t)(b * Tlen + qrow_g) * Cdim + h * HDim + half * 32;
#pragma unroll
        for (int c = 0; c < 32; c += 2) {
            __half2 hv = __floats2half2_rn(orow[c] * inv, orow[c + 1] * inv);
            *reinterpret_cast<__half2*>(out + c) = hv;
        }
    }
}

// -------------------------------- launcher ---------------------------------
extern "C" void kernel_launch(void* const* d_in, const int* in_sizes, int n_in,
                              void* d_out, int out_size)
{
    const float* x           = (const float*)d_in[0];
    const float* ln1_g       = (const float*)d_in[1];
    const float* ln1_b       = (const float*)d_in[2];
    const float* w_qkv       = (const float*)d_in[3];
    const float* b_qkv       = (const float*)d_in[4];
    const float* w_attn_proj = (const float*)d_in[5];
    const float* b_attn_proj = (const float*)d_in[6];
    const float* ln2_g       = (const float*)d_in[7];
    const float* ln2_b       = (const float*)d_in[8];
    const float* w_fc        = (const float*)d_in[9];
    const float* b_fc        = (const float*)d_in[10];
    const float* w_mlp_proj  = (const float*)d_in[11];
    const float* b_mlp_proj  = (const float*)d_in[12];
    float* out = (float*)d_out;

    float *X1;
    __half *H16, *QKV16, *ATT16, *FF16, *Wq16, *Wa16, *Wf16, *Wm16;
    cudaGetSymbolAddress((void**)&X1,    g_X1);
    cudaGetSymbolAddress((void**)&H16,   g_H16);
    cudaGetSymbolAddress((void**)&QKV16, g_QKV16);
    cudaGetSymbolAddress((void**)&ATT16, g_ATT16);
    cudaGetSymbolAddress((void**)&FF16,  g_FF16);
    cudaGetSymbolAddress((void**)&Wq16,  g_Wq16);
    cudaGetSymbolAddress((void**)&Wa16,  g_Wa16);
    cudaGetSymbolAddress((void**)&Wf16,  g_Wf16);
    cudaGetSymbolAddress((void**)&Wm16,  g_Wm16);

    cudaFuncSetAttribute(gemm_h<0,1>, cudaFuncAttributeMaxDynamicSharedMemorySize, GEMM_SMEM);
    cudaFuncSetAttribute(gemm_h<1,1>, cudaFuncAttributeMaxDynamicSharedMemorySize, GEMM_SMEM);
    cudaFuncSetAttribute(gemm_h<2,0>, cudaFuncAttributeMaxDynamicSharedMemorySize, GEMM_SMEM);
    cudaFuncSetAttribute(flash_wmma, cudaFuncAttributeMaxDynamicSharedMemorySize, FLASH_SMEM);

    // weight conversions fp32 -> fp16
    cvt_half_kernel<<<(3*Cdim*Cdim/4 + 255)/256, 256>>>(w_qkv, Wq16, 3*Cdim*Cdim/4);
    cvt_half_kernel<<<(Cdim*Cdim/4 + 255)/256, 256>>>(w_attn_proj, Wa16, Cdim*Cdim/4);
    cvt_half_kernel<<<(Cdim*FFdim/4 + 255)/256, 256>>>(w_fc, Wf16, Cdim*FFdim/4);
    cvt_half_kernel<<<(FFdim*Cdim/4 + 255)/256, 256>>>(w_mlp_proj, Wm16, FFdim*Cdim/4);

    // 1. h = LN1(x)                      (fp16 out)
    ln_kernel<<<Mrows, 256>>>(x, ln1_g, ln1_b, H16);
    // 2. qkv = h @ w_qkv + b             (fp16 out)
    gemm_h<0,1><<<dim3(3 * Cdim / BN, Mrows / BM), 256, GEMM_SMEM>>>(
        H16, Wq16, b_qkv, nullptr, QKV16, Mrows, 3 * Cdim, Cdim);
    // 3. causal flash attention (wmma)   (fp16 out)
    flash_wmma<<<dim3(Tlen / 64, Bsz * NHead), 128, FLASH_SMEM>>>(QKV16, ATT16);
    // 4. x1 = x + attn @ w_attn_proj + b (fp32 out)
    gemm_h<2,0><<<dim3(Cdim / BN, Mrows / BM), 256, GEMM_SMEM>>>(
        ATT16, Wa16, b_attn_proj, x, X1, Mrows, Cdim, Cdim);
    // 5. h = LN2(x1)                     (fp16 out)
    ln_kernel<<<Mrows, 256>>>(X1, ln2_g, ln2_b, H16);
    // 6. ff = gelu(h @ w_fc + b)         (fp16 out)
    gemm_h<1,1><<<dim3(FFdim / BN, Mrows / BM), 256, GEMM_SMEM>>>(
        H16, Wf16, b_fc, nullptr, FF16, Mrows, FFdim, Cdim);
    // 7. out = x1 + ff @ w_mlp_proj + b  (fp32 out)
    gemm_h<2,0><<<dim3(Cdim / BN, Mrows / BM), 256, GEMM_SMEM>>>(
        FF16, Wm16, b_mlp_proj, X1, out, Mrows, Cdim, FFdim);
}

// round 6
// speedup vs baseline: 4.8927x; 1.0041x over previous
#include <cuda_runtime.h>
#include <cuda_fp16.h>
#include <math.h>
#include <stdint.h>
#include <mma.h>

using namespace nvcuda;

// ---------------------------------------------------------------------------
// TransformerBlock B=4,T=2048,C=1024,NH=16,HD=64,FF=4096 fp32.
// R5: GEMM -> 128x256x32 tiles, 64x64 warptiles, 3-stage cp.async ring.
//     fp16 wmma flash attention + LN unchanged.
// ---------------------------------------------------------------------------

#define Bsz   4
#define Tlen  2048
#define Cdim  1024
#define NHead 16
#define HDim  64
#define FFdim 4096
#define Mrows (Bsz * Tlen)   // 8192

// ------------------------- scratch (device globals) ------------------------
__device__ float  g_X1 [Mrows * Cdim];
__device__ __half g_H16  [Mrows * Cdim];
__device__ __half g_QKV16[Mrows * 3 * Cdim];
__device__ __half g_ATT16[Mrows * Cdim];
__device__ __half g_FF16 [Mrows * FFdim];
__device__ __half g_Wq16[Cdim * 3 * Cdim];
__device__ __half g_Wa16[Cdim * Cdim];
__device__ __half g_Wf16[Cdim * FFdim];
__device__ __half g_Wm16[FFdim * Cdim];

// --------------------------- fp32 -> fp16 convert --------------------------
__global__ void __launch_bounds__(256)
cvt_half_kernel(const float* __restrict__ in, __half* __restrict__ out, int n4)
{
    int i = blockIdx.x * 256 + threadIdx.x;
    if (i < n4) {
        float4 v = reinterpret_cast<const float4*>(in)[i];
        __half2 h0 = __floats2half2_rn(v.x, v.y);
        __half2 h1 = __floats2half2_rn(v.z, v.w);
        uint2 o = { *(uint32_t*)&h0, *(uint32_t*)&h1 };
        reinterpret_cast<uint2*>(out)[i] = o;
    }
}

// ------------------------------- LayerNorm ---------------------------------
__global__ void __launch_bounds__(256)
ln_kernel(const float* __restrict__ X, const float* __restrict__ g,
          const float* __restrict__ b, __half* __restrict__ Y)
{
    int row = blockIdx.x;
    int tid = threadIdx.x;
    const float4* xr = reinterpret_cast<const float4*>(X + (size_t)row * Cdim);
    float4 v = xr[tid];
    float sum = v.x + v.y + v.z + v.w;
    float sq  = v.x*v.x + v.y*v.y + v.z*v.z + v.w*v.w;

    __shared__ float s1[256], s2[256];
    s1[tid] = sum; s2[tid] = sq;
    __syncthreads();
    for (int st = 128; st > 0; st >>= 1) {
        if (tid < st) { s1[tid] += s1[tid + st]; s2[tid] += s2[tid + st]; }
        __syncthreads();
    }
    float mu   = s1[0] * (1.0f / Cdim);
    float var  = s2[0] * (1.0f / Cdim) - mu * mu;
    float rstd = rsqrtf(var + 1e-5f);

    const float4 gg = reinterpret_cast<const float4*>(g)[tid];
    const float4 bb = reinterpret_cast<const float4*>(b)[tid];
    __half2 h0 = __floats2half2_rn((v.x - mu) * rstd * gg.x + bb.x,
                                   (v.y - mu) * rstd * gg.y + bb.y);
    __half2 h1 = __floats2half2_rn((v.z - mu) * rstd * gg.z + bb.z,
                                   (v.w - mu) * rstd * gg.w + bb.w);
    uint2 o = { *(uint32_t*)&h0, *(uint32_t*)&h1 };
    reinterpret_cast<uint2*>(Y + (size_t)row * Cdim)[tid] = o;
}

// ------------------------------ common helpers -----------------------------
__device__ __forceinline__ float gelu_f(float x)
{
    float x3 = x * x * x;
    float t  = tanhf(0.7978845608028654f * (x + 0.044715f * x3));
    return 0.5f * x * (1.0f + t);
}

#define CP_ASYNC16(dst, src) \
    asm volatile("cp.async.cg.shared.global [%0], [%1], 16;" :: "r"(dst), "l"(src))
#define CP_COMMIT()   asm volatile("cp.async.commit_group;" ::: "memory")
#define CP_WAIT(n)    asm volatile("cp.async.wait_group %0;" :: "n"(n) : "memory")

__device__ __forceinline__ uint32_t smem_u32(const void* p) {
    uint32_t a;
    asm("{ .reg .u64 t; cvta.to.shared.u64 t, %1; cvt.u32.u64 %0, t; }"
        : "=r"(a) : "l"(p));
    return a;
}

// ----------------------------- fp16 wmma GEMM ------------------------------
// 128x256x32 tile, 8 warps (2x4), 64x64 warptile, 3-stage cp.async ring.
static constexpr int BM = 128, BN = 256, BK = 32;
static constexpr int LDA = 40;    // halves; 80B row stride (LDSM conflict-free)
static constexpr int LDB = 264;   // halves; 528B row stride
static constexpr int A_BYTES = BM * LDA * 2;       // 10240
static constexpr int B_BYTES = BK * LDB * 2;       // 16896
static constexpr int STAGE   = A_BYTES + B_BYTES;  // 27136
static constexpr int NSTG    = 3;
static constexpr int LDC = 260;                    // fp32 epilogue stride
static constexpr int GEMM_SMEM = BM * LDC * 4;     // 133120 (> 3*STAGE=81408)

// EPI: 0 none, 1 gelu, 2 +R.  OUTH: 1 fp16 out, 0 fp32 out.
template<int EPI, int OUTH>
__global__ void __launch_bounds__(256, 1)
gemm_h(const __half* __restrict__ A, const __half* __restrict__ W,
       const float* __restrict__ bias, const float* __restrict__ R,
       void* __restrict__ Cout, int M, int N, int K)
{
    extern __shared__ __align__(128) char smem[];
    uint32_t sA_u[NSTG], sB_u[NSTG];
    const __half* sA[NSTG];
    const __half* sB[NSTG];
#pragma unroll
    for (int i = 0; i < NSTG; i++) {
        sA[i] = (const __half*)(smem + i * STAGE);
        sB[i] = (const __half*)(smem + i * STAGE + A_BYTES);
        sA_u[i] = smem_u32(sA[i]);
        sB_u[i] = smem_u32(sB[i]);
    }

    int tid = threadIdx.x;
    int wid = tid >> 5;
    int wm  = wid >> 2;          // 0..1 (64-row slab)
    int wn  = wid & 3;           // 0..3 (64-col slab)
    int m0  = blockIdx.y * BM;
    int n0  = blockIdx.x * BN;

    wmma::fragment<wmma::accumulator, 16, 16, 16, float> acc[4][4];
#pragma unroll
    for (int i = 0; i < 4; i++)
#pragma unroll
        for (int j = 0; j < 4; j++) wmma::fill_fragment(acc[i][j], 0.0f);

    int nk = K / BK;

    // stage loader: A 512 chunks (2/thr), B 1024 chunks (4/thr)
    auto issue_stage = [&](int s, int buf) {
        const __half* Ab = A + (size_t)m0 * K + s * BK;
        const __half* Wb = W + (size_t)s * BK * N + n0;
#pragma unroll
        for (int i = 0; i < 2; i++) {
            int f = tid + i * 256;
            int ra = f >> 2, ca = f & 3;
            CP_ASYNC16(sA_u[buf] + (ra * LDA + ca * 8) * 2,
                       Ab + (size_t)ra * K + ca * 8);
        }
#pragma unroll
        for (int i = 0; i < 4; i++) {
            int f = tid + i * 256;
            int rb = f >> 5, cb = f & 31;
            CP_ASYNC16(sB_u[buf] + (rb * LDB + cb * 8) * 2,
                       Wb + (size_t)rb * N + cb * 8);
        }
        CP_COMMIT();
    };

    // prologue: fill 2 stages
    issue_stage(0, 0);
    if (nk > 1) issue_stage(1, 1);

    for (int s = 0; s < nk; ++s) {
        int buf = s % NSTG;
        if (s + 2 < nk) {
            issue_stage(s + 2, (s + 2) % NSTG);
            CP_WAIT(2);
        } else if (s + 1 < nk) {
            CP_WAIT(1);
        } else {
            CP_WAIT(0);
        }
        __syncthreads();

        const __half* a_base = sA[buf] + (wm * 64) * LDA;
        const __half* b_base = sB[buf] + wn * 64;
#pragma unroll
        for (int ks = 0; ks < 2; ++ks) {
            wmma::fragment<wmma::matrix_a, 16, 16, 16, __half, wmma::row_major> fa[4];
#pragma unroll
            for (int mi = 0; mi < 4; mi++)
                wmma::load_matrix_sync(fa[mi], a_base + mi * 16 * LDA + ks * 16, LDA);
#pragma unroll
            for (int ni = 0; ni < 4; ni++) {
                wmma::fragment<wmma::matrix_b, 16, 16, 16, __half, wmma::row_major> fb;
                wmma::load_matrix_sync(fb, b_base + ks * 16 * LDB + ni * 16, LDB);
#pragma unroll
                for (int mi = 0; mi < 4; mi++)
                    wmma::mma_sync(acc[mi][ni], fa[mi], fb, acc[mi][ni]);
            }
        }
        __syncthreads();
    }

    // ---- epilogue: acc -> smem(fp32) -> fused bias/gelu/residual -> out ----
    float* sC = (float*)smem;
#pragma unroll
    for (int mi = 0; mi < 4; mi++)
#pragma unroll
        for (int ni = 0; ni < 4; ni++)
            wmma::store_matrix_sync(
                sC + (wm * 64 + mi * 16) * LDC + wn * 64 + ni * 16,
                acc[mi][ni], LDC, wmma::mem_row_major);
    __syncthreads();

    int row  = tid >> 1;                 // 0..127
    int cb0  = (tid & 1) * 128;          // 0 or 128
    int grow = m0 + row;
    const float* rrow = (EPI == 2) ? (R + (size_t)grow * N + n0 + cb0) : nullptr;
    const float* srow = sC + row * LDC + cb0;
    const float* brow = bias + n0 + cb0;
    float*  cfrow = (float*)Cout  + (size_t)grow * N + n0 + cb0;
    __half* chrow = (__half*)Cout + (size_t)grow * N + n0 + cb0;
#pragma unroll
    for (int j4 = 0; j4 < 32; ++j4) {
        float4 v  = *reinterpret_cast<const float4*>(srow + j4 * 4);
        float4 bi = *reinterpret_cast<const float4*>(brow + j4 * 4);
        v.x += bi.x; v.y += bi.y; v.z += bi.z; v.w += bi.w;
        if (EPI == 1) {
            v.x = gelu_f(v.x); v.y = gelu_f(v.y);
            v.z = gelu_f(v.z); v.w = gelu_f(v.w);
        } else if (EPI == 2) {
            float4 r = *reinterpret_cast<const float4*>(rrow + j4 * 4);
            v.x += r.x; v.y += r.y; v.z += r.z; v.w += r.w;
        }
        if (OUTH) {
            __half2 h0 = __floats2half2_rn(v.x, v.y);
            __half2 h1 = __floats2half2_rn(v.z, v.w);
            uint2 o = { *(uint32_t*)&h0, *(uint32_t*)&h1 };
            *reinterpret_cast<uint2*>(chrow + j4 * 4) = o;
        } else {
            *reinterpret_cast<float4*>(cfrow + j4 * 4) = v;
        }
    }
}

// ------------------------- wmma fp16 flash attention -----------------------
static constexpr int LQ = 72;
static constexpr int LS = 68;
static constexpr int Q_OFF = 0;
static constexpr int K_OFF = Q_OFF + 64 * LQ * 2;
static constexpr int V_OFF = K_OFF + 64 * LQ * 2;
static constexpr int P_OFF = V_OFF + 64 * LQ * 2;
static constexpr int S_OFF = P_OFF + 64 * LQ * 2;
static constexpr int O_OFF = S_OFF + 64 * LS * 4;
static constexpr int M_OFF = O_OFF + 64 * LS * 4;
static constexpr int L_OFF = M_OFF + 64 * 4;
static constexpr int FLASH_SMEM = L_OFF + 64 * 4;

__global__ void __launch_bounds__(128)
flash_wmma(const __half* __restrict__ QKV, __half* __restrict__ ATT)
{
    extern __shared__ __align__(128) char smem[];
    __half* Qs = (__half*)(smem + Q_OFF);
    __half* Ks = (__half*)(smem + K_OFF);
    __half* Vs = (__half*)(smem + V_OFF);
    __half* Ps = (__half*)(smem + P_OFF);
    float*  Ss = (float*)(smem + S_OFF);
    float*  Os = (float*)(smem + O_OFF);
    float*  mrow = (float*)(smem + M_OFF);
    float*  lrow = (float*)(smem + L_OFF);
    uint32_t Qu = smem_u32(Qs), Ku = smem_u32(Ks), Vu = smem_u32(Vs);

    int tid  = threadIdx.x;
    int w    = tid >> 5;
    int lane = tid & 31;
    int qt   = gridDim.x - 1 - blockIdx.x;
    int bh   = blockIdx.y;
    int b    = bh >> 4;
    int h    = bh & 15;
    int q0   = qt * 64;

    for (int i = tid; i < 64 * LS; i += 128) Os[i] = 0.0f;
    if (tid < 64) { mrow[tid] = -1e30f; lrow[tid] = 0.0f; }

    const __half* Qg = QKV + (size_t)(b * Tlen + q0) * (3 * Cdim) + h * HDim;
#pragma unroll
    for (int i = 0; i < 4; i++) {
        int f = tid + i * 128;
        int r = f >> 3, c8 = f & 7;
        CP_ASYNC16(Qu + (r * LQ + c8 * 8) * 2, Qg + (size_t)r * (3 * Cdim) + c8 * 8);
    }
    CP_COMMIT();
    CP_WAIT(0);
    __syncthreads();

    int srow_q = w * 16 + (lane >> 1);
    int half   = lane & 1;
    int qrow_g = q0 + srow_q;

    for (int j0 = 0; j0 <= q0; j0 += 64) {
        const __half* Kg = QKV + (size_t)(b * Tlen + j0) * (3 * Cdim) + Cdim + h * HDim;
        const __half* Vg = Kg + Cdim;
#pragma unroll
        for (int i = 0; i < 4; i++) {
            int f = tid + i * 128;
            int r = f >> 3, c8 = f & 7;
            CP_ASYNC16(Ku + (r * LQ + c8 * 8) * 2, Kg + (size_t)r * (3 * Cdim) + c8 * 8);
            CP_ASYNC16(Vu + (r * LQ + c8 * 8) * 2, Vg + (size_t)r * (3 * Cdim) + c8 * 8);
        }
        CP_COMMIT();
        CP_WAIT(0);
        __syncthreads();

        {
            wmma::fragment<wmma::matrix_a, 16, 16, 16, __half, wmma::row_major> fa[4];
#pragma unroll
            for (int ks = 0; ks < 4; ks++)
                wmma::load_matrix_sync(fa[ks], Qs + (w * 16) * LQ + ks * 16, LQ);
#pragma unroll
            for (int n = 0; n < 4; n++) {
                wmma::fragment<wmma::accumulator, 16, 16, 16, float> accS;
                wmma::fill_fragment(accS, 0.0f);
#pragma unroll
                for (int ks = 0; ks < 4; ks++) {
                    wmma::fragment<wmma::matrix_b, 16, 16, 16, __half, wmma::col_major> fb;
                    wmma::load_matrix_sync(fb, Ks + (n * 16) * LQ + ks * 16, LQ);
                    wmma::mma_sync(accS, fa[ks], fb, accS);
                }
                wmma::store_matrix_sync(Ss + (w * 16) * LS + n * 16, accS, LS,
                                        wmma::mem_row_major);
            }
        }
        __syncthreads();

        {
            float* sr = Ss + srow_q * LS + half * 32;
            bool diag = (j0 == q0);
            float sv[32];
            float tmax = -1e30f;
#pragma unroll
            for (int c = 0; c < 32; c++) {
                float s = sr[c] * 0.125f;
                if (diag && (j0 + half * 32 + c > qrow_g)) s = -1e30f;
                sv[c] = s;
                tmax = fmaxf(tmax, s);
            }
            tmax = fmaxf(tmax, __shfl_xor_sync(0xFFFFFFFFu, tmax, 1));
            float m_old = mrow[srow_q];
            float m_new = fmaxf(m_old, tmax);
            float scale = __expf(m_old - m_new);
            float sum = 0.0f;
            __half* pr = Ps + srow_q * LQ + half * 32;
#pragma unroll
            for (int c = 0; c < 32; c += 2) {
                float p0 = __expf(sv[c]   - m_new);
                float p1 = __expf(sv[c+1] - m_new);
                sum += p0 + p1;
                __half2 hp = __floats2half2_rn(p0, p1);
                *reinterpret_cast<__half2*>(pr + c) = hp;
            }
            sum += __shfl_xor_sync(0xFFFFFFFFu, sum, 1);
            if (half == 0) {
                mrow[srow_q] = m_new;
                lrow[srow_q] = lrow[srow_q] * scale + sum;
            }
            float* orow = Os + srow_q * LS + half * 32;
#pragma unroll
            for (int c = 0; c < 32; c++) orow[c] *= scale;
        }
        __syncthreads();

        {
            wmma::fragment<wmma::matrix_a, 16, 16, 16, __half, wmma::row_major> fp[4];
#pragma unroll
            for (int ks = 0; ks < 4; ks++)
                wmma::load_matrix_sync(fp[ks], Ps + (w * 16) * LQ + ks * 16, LQ);
#pragma unroll
            for (int n = 0; n < 4; n++) {
                wmma::fragment<wmma::accumulator, 16, 16, 16, float> accO;
                wmma::load_matrix_sync(accO, Os + (w * 16) * LS + n * 16, LS,
                                       wmma::mem_row_major);
#pragma unroll
                for (int ks = 0; ks < 4; ks++) {
                    wmma::fragment<wmma::matrix_b, 16, 16, 16, __half, wmma::row_major> fv;
                    wmma::load_matrix_sync(fv, Vs + (ks * 16) * LQ + n * 16, LQ);
                    wmma::mma_sync(accO, fp[ks], fv, accO);
                }
                wmma::store_matrix_sync(Os + (w * 16) * LS + n * 16, accO, LS,
                                        wmma::mem_row_major);
            }
        }
        __syncthreads();
    }

    {
        float inv = 1.0f / lrow[srow_q];
        const float* orow = Os + srow_q * LS + half * 32;
        __half* out = ATT + (size_t)(b * Tlen + qrow_g) * Cdim + h * HDim + half * 32;
#pragma unroll
        for (int c = 0; c < 32; c += 2) {
            __half2 hv = __floats2half2_rn(orow[c] * inv, orow[c + 1] * inv);
            *reinterpret_cast<__half2*>(out + c) = hv;
        }
    }
}

// -------------------------------- launcher ---------------------------------
extern "C" void kernel_launch(void* const* d_in, const int* in_sizes, int n_in,
                              void* d_out, int out_size)
{
    const float* x           = (const float*)d_in[0];
    const float* ln1_g       = (const float*)d_in[1];
    const float* ln1_b       = (const float*)d_in[2];
    const float* w_qkv       = (const float*)d_in[3];
    const float* b_qkv       = (const float*)d_in[4];
    const float* w_attn_proj = (const float*)d_in[5];
    const float* b_attn_proj = (const float*)d_in[6];
    const float* ln2_g       = (const float*)d_in[7];
    const float* ln2_b       = (const float*)d_in[8];
    const float* w_fc        = (const float*)d_in[9];
    const float* b_fc        = (const float*)d_in[10];
    const float* w_mlp_proj  = (const float*)d_in[11];
    const float* b_mlp_proj  = (const float*)d_in[12];
    float* out = (float*)d_out;

    float *X1;
    __half *H16, *QKV16, *ATT16, *FF16, *Wq16, *Wa16, *Wf16, *Wm16;
    cudaGetSymbolAddress((void**)&X1,    g_X1);
    cudaGetSymbolAddress((void**)&H16,   g_H16);
    cudaGetSymbolAddress((void**)&QKV16, g_QKV16);
    cudaGetSymbolAddress((void**)&ATT16, g_ATT16);
    cudaGetSymbolAddress((void**)&FF16,  g_FF16);
    cudaGetSymbolAddress((void**)&Wq16,  g_Wq16);
    cudaGetSymbolAddress((void**)&Wa16,  g_Wa16);
    cudaGetSymbolAddress((void**)&Wf16,  g_Wf16);
    cudaGetSymbolAddress((void**)&Wm16,  g_Wm16);

    cudaFuncSetAttribute(gemm_h<0,1>, cudaFuncAttributeMaxDynamicSharedMemorySize, GEMM_SMEM);
    cudaFuncSetAttribute(gemm_h<1,1>, cudaFuncAttributeMaxDynamicSharedMemorySize, GEMM_SMEM);
    cudaFuncSetAttribute(gemm_h<2,0>, cudaFuncAttributeMaxDynamicSharedMemorySize, GEMM_SMEM);
    cudaFuncSetAttribute(flash_wmma, cudaFuncAttributeMaxDynamicSharedMemorySize, FLASH_SMEM);

    cvt_half_kernel<<<(3*Cdim*Cdim/4 + 255)/256, 256>>>(w_qkv, Wq16, 3*Cdim*Cdim/4);
    cvt_half_kernel<<<(Cdim*Cdim/4 + 255)/256, 256>>>(w_attn_proj, Wa16, Cdim*Cdim/4);
    cvt_half_kernel<<<(Cdim*FFdim/4 + 255)/256, 256>>>(w_fc, Wf16, Cdim*FFdim/4);
    cvt_half_kernel<<<(FFdim*Cdim/4 + 255)/256, 256>>>(w_mlp_proj, Wm16, FFdim*Cdim/4);

    // 1. h = LN1(x)                      (fp16 out)
    ln_kernel<<<Mrows, 256>>>(x, ln1_g, ln1_b, H16);
    // 2. qkv = h @ w_qkv + b             (fp16 out)
    gemm_h<0,1><<<dim3(3 * Cdim / BN, Mrows / BM), 256, GEMM_SMEM>>>(
        H16, Wq16, b_qkv, nullptr, QKV16, Mrows, 3 * Cdim, Cdim);
    // 3. causal flash attention (wmma)   (fp16 out)
    flash_wmma<<<dim3(Tlen / 64, Bsz * NHead), 128, FLASH_SMEM>>>(QKV16, ATT16);
    // 4. x1 = x + attn @ w_attn_proj + b (fp32 out)
    gemm_h<2,0><<<dim3(Cdim / BN, Mrows / BM), 256, GEMM_SMEM>>>(
        ATT16, Wa16, b_attn_proj, x, X1, Mrows, Cdim, Cdim);
    // 5. h = LN2(x1)                     (fp16 out)
    ln_kernel<<<Mrows, 256>>>(X1, ln2_g, ln2_b, H16);
    // 6. ff = gelu(h @ w_fc + b)         (fp16 out)
    gemm_h<1,1><<<dim3(FFdim / BN, Mrows / BM), 256, GEMM_SMEM>>>(
        H16, Wf16, b_fc, nullptr, FF16, Mrows, FFdim, Cdim);
    // 7. out = x1 + ff @ w_mlp_proj + b  (fp32 out)
    gemm_h<2,0><<<dim3(Cdim / BN, Mrows / BM), 256, GEMM_SMEM>>>(
        FF16, Wm16, b_mlp_proj, X1, out, Mrows, Cdim, FFdim);
}

// round 7
// speedup vs baseline: 4.9839x; 1.0186x over previous
#include <cuda_runtime.h>
#include <cuda_fp16.h>
#include <math.h>
#include <stdint.h>
#include <mma.h>

using namespace nvcuda;

// ---------------------------------------------------------------------------
// TransformerBlock B=4,T=2048,C=1024,NH=16,HD=64,FF=4096 fp32.
// R6: GEMM 128x128xBK64 double-buffered (2 CTA/SM); flash with double-buffered
//     K/V tiles; warp-per-row LayerNorm.
// ---------------------------------------------------------------------------

#define Bsz   4
#define Tlen  2048
#define Cdim  1024
#define NHead 16
#define HDim  64
#define FFdim 4096
#define Mrows (Bsz * Tlen)   // 8192

// ------------------------- scratch (device globals) ------------------------
__device__ float  g_X1 [Mrows * Cdim];
__device__ __half g_H16  [Mrows * Cdim];
__device__ __half g_QKV16[Mrows * 3 * Cdim];
__device__ __half g_ATT16[Mrows * Cdim];
__device__ __half g_FF16 [Mrows * FFdim];
__device__ __half g_Wq16[Cdim * 3 * Cdim];
__device__ __half g_Wa16[Cdim * Cdim];
__device__ __half g_Wf16[Cdim * FFdim];
__device__ __half g_Wm16[FFdim * Cdim];

// --------------------------- fp32 -> fp16 convert --------------------------
__global__ void __launch_bounds__(256)
cvt_half_kernel(const float* __restrict__ in, __half* __restrict__ out, int n4)
{
    int i = blockIdx.x * 256 + threadIdx.x;
    if (i < n4) {
        float4 v = reinterpret_cast<const float4*>(in)[i];
        __half2 h0 = __floats2half2_rn(v.x, v.y);
        __half2 h1 = __floats2half2_rn(v.z, v.w);
        uint2 o = { *(uint32_t*)&h0, *(uint32_t*)&h1 };
        reinterpret_cast<uint2*>(out)[i] = o;
    }
}

// ------------------------ LayerNorm (warp per row) -------------------------
__global__ void __launch_bounds__(256)
ln_kernel(const float* __restrict__ X, const float* __restrict__ g,
          const float* __restrict__ b, __half* __restrict__ Y)
{
    int w    = threadIdx.x >> 5;
    int lane = threadIdx.x & 31;
    int row  = blockIdx.x * 8 + w;

    const float4* xr = reinterpret_cast<const float4*>(X + (size_t)row * Cdim);
    float4 v[8];
    float sum = 0.0f, sq = 0.0f;
#pragma unroll
    for (int i = 0; i < 8; i++) {
        v[i] = xr[lane + 32 * i];
        sum += v[i].x + v[i].y + v[i].z + v[i].w;
        sq  += v[i].x*v[i].x + v[i].y*v[i].y + v[i].z*v[i].z + v[i].w*v[i].w;
    }
#pragma unroll
    for (int st = 16; st > 0; st >>= 1) {
        sum += __shfl_xor_sync(0xFFFFFFFFu, sum, st);
        sq  += __shfl_xor_sync(0xFFFFFFFFu, sq,  st);
    }
    float mu   = sum * (1.0f / Cdim);
    float var  = sq  * (1.0f / Cdim) - mu * mu;
    float rstd = rsqrtf(var + 1e-5f);

    const float4* gr = reinterpret_cast<const float4*>(g);
    const float4* br = reinterpret_cast<const float4*>(b);
    uint2* yr = reinterpret_cast<uint2*>(Y + (size_t)row * Cdim);
#pragma unroll
    for (int i = 0; i < 8; i++) {
        float4 gg = gr[lane + 32 * i];
        float4 bb = br[lane + 32 * i];
        __half2 h0 = __floats2half2_rn((v[i].x - mu) * rstd * gg.x + bb.x,
                                       (v[i].y - mu) * rstd * gg.y + bb.y);
        __half2 h1 = __floats2half2_rn((v[i].z - mu) * rstd * gg.z + bb.z,
                                       (v[i].w - mu) * rstd * gg.w + bb.w);
        uint2 o = { *(uint32_t*)&h0, *(uint32_t*)&h1 };
        yr[lane + 32 * i] = o;
    }
}

// ------------------------------ common helpers -----------------------------
__device__ __forceinline__ float gelu_f(float x)
{
    float x3 = x * x * x;
    float t  = tanhf(0.7978845608028654f * (x + 0.044715f * x3));
    return 0.5f * x * (1.0f + t);
}

#define CP_ASYNC16(dst, src) \
    asm volatile("cp.async.cg.shared.global [%0], [%1], 16;" :: "r"(dst), "l"(src))
#define CP_COMMIT()   asm volatile("cp.async.commit_group;" ::: "memory")
#define CP_WAIT(n)    asm volatile("cp.async.wait_group %0;" :: "n"(n) : "memory")

__device__ __forceinline__ uint32_t smem_u32(const void* p) {
    uint32_t a;
    asm("{ .reg .u64 t; cvta.to.shared.u64 t, %1; cvt.u32.u64 %0, t; }"
        : "=r"(a) : "l"(p));
    return a;
}

// ----------------------------- fp16 wmma GEMM ------------------------------
// 128x128x64 tiles, 8 warps (2x4), 64x32 warptile, double-buffered, 2 CTA/SM.
static constexpr int BM = 128, BN = 128, BK = 64;
static constexpr int LDA = 72;    // halves; 144B row stride
static constexpr int LDB = 136;   // halves; 272B row stride
static constexpr int A_BYTES = BM * LDA * 2;       // 18432
static constexpr int B_BYTES = BK * LDB * 2;       // 17408
static constexpr int STAGE   = A_BYTES + B_BYTES;  // 35840
static constexpr int LDC = 132;
static constexpr int GEMM_SMEM = 2 * STAGE;        // 71680 (> 128*132*4=67584)

// EPI: 0 none, 1 gelu, 2 +R.  OUTH: 1 fp16 out, 0 fp32 out.
template<int EPI, int OUTH>
__global__ void __launch_bounds__(256, 2)
gemm_h(const __half* __restrict__ A, const __half* __restrict__ W,
       const float* __restrict__ bias, const float* __restrict__ R,
       void* __restrict__ Cout, int M, int N, int K)
{
    extern __shared__ __align__(128) char smem[];
    const __half* sA[2] = { (const __half*)smem, (const __half*)(smem + STAGE) };
    const __half* sB[2] = { (const __half*)(smem + A_BYTES),
                            (const __half*)(smem + STAGE + A_BYTES) };
    uint32_t sA_u[2] = { smem_u32(sA[0]), smem_u32(sA[1]) };
    uint32_t sB_u[2] = { smem_u32(sB[0]), smem_u32(sB[1]) };

    int tid = threadIdx.x;
    int wid = tid >> 5;
    int wm  = wid >> 2;
    int wn  = wid & 3;
    int m0  = blockIdx.y * BM;
    int n0  = blockIdx.x * BN;

    wmma::fragment<wmma::accumulator, 16, 16, 16, float> acc[4][2];
#pragma unroll
    for (int i = 0; i < 4; i++)
#pragma unroll
        for (int j = 0; j < 2; j++) wmma::fill_fragment(acc[i][j], 0.0f);

    int nk = K / BK;

    auto issue_stage = [&](int s, int buf) {
        const __half* Ab = A + (size_t)m0 * K + s * BK;
        const __half* Wb = W + (size_t)s * BK * N + n0;
#pragma unroll
        for (int i = 0; i < 4; i++) {
            int f = tid + i * 256;
            int ra = f >> 3, ca = f & 7;          // 128 rows x 8 chunks
            CP_ASYNC16(sA_u[buf] + (ra * LDA + ca * 8) * 2,
                       Ab + (size_t)ra * K + ca * 8);
            int rb = f >> 4, cb = f & 15;         // 64 rows x 16 chunks
            CP_ASYNC16(sB_u[buf] + (rb * LDB + cb * 8) * 2,
                       Wb + (size_t)rb * N + cb * 8);
        }
        CP_COMMIT();
    };

    issue_stage(0, 0);

    for (int s = 0; s < nk; ++s) {
        int buf = s & 1;
        if (s + 1 < nk) {
            issue_stage(s + 1, buf ^ 1);
            CP_WAIT(1);
        } else {
            CP_WAIT(0);
        }
        __syncthreads();

        const __half* a_base = sA[buf] + (wm * 64) * LDA;
        const __half* b_base = sB[buf] + wn * 32;
#pragma unroll
        for (int ks = 0; ks < 4; ++ks) {
            wmma::fragment<wmma::matrix_a, 16, 16, 16, __half, wmma::row_major> fa[4];
            wmma::fragment<wmma::matrix_b, 16, 16, 16, __half, wmma::row_major> fb[2];
#pragma unroll
            for (int mi = 0; mi < 4; mi++)
                wmma::load_matrix_sync(fa[mi], a_base + mi * 16 * LDA + ks * 16, LDA);
#pragma unroll
            for (int ni = 0; ni < 2; ni++)
                wmma::load_matrix_sync(fb[ni], b_base + ks * 16 * LDB + ni * 16, LDB);
#pragma unroll
            for (int mi = 0; mi < 4; mi++)
#pragma unroll
                for (int ni = 0; ni < 2; ni++)
                    wmma::mma_sync(acc[mi][ni], fa[mi], fb[ni], acc[mi][ni]);
        }
        __syncthreads();
    }

    float* sC = (float*)smem;
#pragma unroll
    for (int mi = 0; mi < 4; mi++)
#pragma unroll
        for (int ni = 0; ni < 2; ni++)
            wmma::store_matrix_sync(
                sC + (wm * 64 + mi * 16) * LDC + wn * 32 + ni * 16,
                acc[mi][ni], LDC, wmma::mem_row_major);
    __syncthreads();

    int row  = tid >> 1;
    int cb0  = (tid & 1) * 64;
    int grow = m0 + row;
    const float* rrow = (EPI == 2) ? (R + (size_t)grow * N + n0 + cb0) : nullptr;
    const float* srow = sC + row * LDC + cb0;
    const float* brow = bias + n0 + cb0;
    float*  cfrow = (float*)Cout  + (size_t)grow * N + n0 + cb0;
    __half* chrow = (__half*)Cout + (size_t)grow * N + n0 + cb0;
#pragma unroll
    for (int j4 = 0; j4 < 16; ++j4) {
        float4 v  = *reinterpret_cast<const float4*>(srow + j4 * 4);
        float4 bi = *reinterpret_cast<const float4*>(brow + j4 * 4);
        v.x += bi.x; v.y += bi.y; v.z += bi.z; v.w += bi.w;
        if (EPI == 1) {
            v.x = gelu_f(v.x); v.y = gelu_f(v.y);
            v.z = gelu_f(v.z); v.w = gelu_f(v.w);
        } else if (EPI == 2) {
            float4 r = *reinterpret_cast<const float4*>(rrow + j4 * 4);
            v.x += r.x; v.y += r.y; v.z += r.z; v.w += r.w;
        }
        if (OUTH) {
            __half2 h0 = __floats2half2_rn(v.x, v.y);
            __half2 h1 = __floats2half2_rn(v.z, v.w);
            uint2 o = { *(uint32_t*)&h0, *(uint32_t*)&h1 };
            *reinterpret_cast<uint2*>(chrow + j4 * 4) = o;
        } else {
            *reinterpret_cast<float4*>(cfrow + j4 * 4) = v;
        }
    }
}

// ------------------------- wmma fp16 flash attention -----------------------
// 128 threads (4 warps), 64 q rows per block, double-buffered K/V tiles of 64.
static constexpr int LQ = 72;
static constexpr int LS = 68;
static constexpr int Q_OFF  = 0;                       // 9216
static constexpr int K_OFF0 = Q_OFF  + 64 * LQ * 2;    //  9216
static constexpr int V_OFF0 = K_OFF0 + 64 * LQ * 2;    // 18432
static constexpr int K_OFF1 = V_OFF0 + 64 * LQ * 2;    // 27648
static constexpr int V_OFF1 = K_OFF1 + 64 * LQ * 2;    // 36864
static constexpr int P_OFF  = V_OFF1 + 64 * LQ * 2;    // 46080
static constexpr int S_OFF  = P_OFF  + 64 * LQ * 2;    // 55296
static constexpr int O_OFF  = S_OFF  + 64 * LS * 4;    // 72704
static constexpr int M_OFF  = O_OFF  + 64 * LS * 4;    // 90112
static constexpr int L_OFF  = M_OFF  + 64 * 4;         // 90368
static constexpr int FLASH_SMEM = L_OFF + 64 * 4;      // 90624

__global__ void __launch_bounds__(128, 2)
flash_wmma(const __half* __restrict__ QKV, __half* __restrict__ ATT)
{
    extern __shared__ __align__(128) char smem[];
    __half* Qs = (__half*)(smem + Q_OFF);
    __half* Ks[2] = { (__half*)(smem + K_OFF0), (__half*)(smem + K_OFF1) };
    __half* Vs[2] = { (__half*)(smem + V_OFF0), (__half*)(smem + V_OFF1) };
    __half* Ps = (__half*)(smem + P_OFF);
    float*  Ss = (float*)(smem + S_OFF);
    float*  Os = (float*)(smem + O_OFF);
    float*  mrow = (float*)(smem + M_OFF);
    float*  lrow = (float*)(smem + L_OFF);
    uint32_t Qu = smem_u32(Qs);
    uint32_t Ku[2] = { smem_u32(Ks[0]), smem_u32(Ks[1]) };
    uint32_t Vu[2] = { smem_u32(Vs[0]), smem_u32(Vs[1]) };

    int tid  = threadIdx.x;
    int w    = tid >> 5;
    int lane = tid & 31;
    int qt   = gridDim.x - 1 - blockIdx.x;     // heavy tiles first
    int bh   = blockIdx.y;
    int b    = bh >> 4;
    int h    = bh & 15;
    int q0   = qt * 64;

    for (int i = tid; i < 64 * LS; i += 128) Os[i] = 0.0f;
    if (tid < 64) { mrow[tid] = -1e30f; lrow[tid] = 0.0f; }

    // KV tile loader
    auto issue_kv = [&](int j0, int buf) {
        const __half* Kg = QKV + (size_t)(b * Tlen + j0) * (3 * Cdim) + Cdim + h * HDim;
        const __half* Vg = Kg + Cdim;
#pragma unroll
        for (int i = 0; i < 4; i++) {
            int f = tid + i * 128;
            int r = f >> 3, c8 = f & 7;
            CP_ASYNC16(Ku[buf] + (r * LQ + c8 * 8) * 2, Kg + (size_t)r * (3 * Cdim) + c8 * 8);
            CP_ASYNC16(Vu[buf] + (r * LQ + c8 * 8) * 2, Vg + (size_t)r * (3 * Cdim) + c8 * 8);
        }
        CP_COMMIT();
    };

    // load Q + first KV tile
    {
        const __half* Qg = QKV + (size_t)(b * Tlen + q0) * (3 * Cdim) + h * HDim;
#pragma unroll
        for (int i = 0; i < 4; i++) {
            int f = tid + i * 128;
            int r = f >> 3, c8 = f & 7;
            CP_ASYNC16(Qu + (r * LQ + c8 * 8) * 2, Qg + (size_t)r * (3 * Cdim) + c8 * 8);
        }
        CP_COMMIT();
        issue_kv(0, 0);
    }

    int srow_q = w * 16 + (lane >> 1);
    int half   = lane & 1;
    int qrow_g = q0 + srow_q;

    for (int j0 = 0; j0 <= q0; j0 += 64) {
        int buf = (j0 >> 6) & 1;
        if (j0 + 64 <= q0) {
            issue_kv(j0 + 64, buf ^ 1);
            CP_WAIT(1);
        } else {
            CP_WAIT(0);
        }
        __syncthreads();

        // ---- S = Q @ K^T ----
        {
            wmma::fragment<wmma::matrix_a, 16, 16, 16, __half, wmma::row_major> fa[4];
#pragma unroll
            for (int ks = 0; ks < 4; ks++)
                wmma::load_matrix_sync(fa[ks], Qs + (w * 16) * LQ + ks * 16, LQ);
#pragma unroll
            for (int n = 0; n < 4; n++) {
                wmma::fragment<wmma::accumulator, 16, 16, 16, float> accS;
                wmma::fill_fragment(accS, 0.0f);
#pragma unroll
                for (int ks = 0; ks < 4; ks++) {
                    wmma::fragment<wmma::matrix_b, 16, 16, 16, __half, wmma::col_major> fb;
                    wmma::load_matrix_sync(fb, Ks[buf] + (n * 16) * LQ + ks * 16, LQ);
                    wmma::mma_sync(accS, fa[ks], fb, accS);
                }
                wmma::store_matrix_sync(Ss + (w * 16) * LS + n * 16, accS, LS,
                                        wmma::mem_row_major);
            }
        }
        __syncthreads();

        // ---- online softmax ----
        {
            float* sr = Ss + srow_q * LS + half * 32;
            bool diag = (j0 == q0);
            float sv[32];
            float tmax = -1e30f;
#pragma unroll
            for (int c = 0; c < 32; c++) {
                float s = sr[c] * 0.125f;
                if (diag && (j0 + half * 32 + c > qrow_g)) s = -1e30f;
                sv[c] = s;
                tmax = fmaxf(tmax, s);
            }
            tmax = fmaxf(tmax, __shfl_xor_sync(0xFFFFFFFFu, tmax, 1));
            float m_old = mrow[srow_q];
            float m_new = fmaxf(m_old, tmax);
            float scale = __expf(m_old - m_new);
            float sum = 0.0f;
            __half* pr = Ps + srow_q * LQ + half * 32;
#pragma unroll
            for (int c = 0; c < 32; c += 2) {
                float p0 = __expf(sv[c]   - m_new);
                float p1 = __expf(sv[c+1] - m_new);
                sum += p0 + p1;
                __half2 hp = __floats2half2_rn(p0, p1);
                *reinterpret_cast<__half2*>(pr + c) = hp;
            }
            sum += __shfl_xor_sync(0xFFFFFFFFu, sum, 1);
            if (half == 0) {
                mrow[srow_q] = m_new;
                lrow[srow_q] = lrow[srow_q] * scale + sum;
            }
            float* orow = Os + srow_q * LS + half * 32;
#pragma unroll
            for (int c = 0; c < 32; c++) orow[c] *= scale;
        }
        __syncthreads();

        // ---- O += P @ V ----
        {
            wmma::fragment<wmma::matrix_a, 16, 16, 16, __half, wmma::row_major> fp[4];
#pragma unroll
            for (int ks = 0; ks < 4; ks++)
                wmma::load_matrix_sync(fp[ks], Ps + (w * 16) * LQ + ks * 16, LQ);
#pragma unroll
            for (int n = 0; n < 4; n++) {
                wmma::fragment<wmma::accumulator, 16, 16, 16, float> accO;
                wmma::load_matrix_sync(accO, Os + (w * 16) * LS + n * 16, LS,
                                       wmma::mem_row_major);
#pragma unroll
                for (int ks = 0; ks < 4; ks++) {
                    wmma::fragment<wmma::matrix_b, 16, 16, 16, __half, wmma::row_major> fv;
                    wmma::load_matrix_sync(fv, Vs[buf] + (ks * 16) * LQ + n * 16, LQ);
                    wmma::mma_sync(accO, fp[ks], fv, accO);
                }
                wmma::store_matrix_sync(Os + (w * 16) * LS + n * 16, accO, LS,
                                        wmma::mem_row_major);
            }
        }
        __syncthreads();
    }

    {
        float inv = 1.0f / lrow[srow_q];
        const float* orow = Os + srow_q * LS + half * 32;
        __half* out = ATT + (size_t)(b * Tlen + qrow_g) * Cdim + h * HDim + half * 32;
#pragma unroll
        for (int c = 0; c < 32; c += 2) {
            __half2 hv = __floats2half2_rn(orow[c] * inv, orow[c + 1] * inv);
            *reinterpret_cast<__half2*>(out + c) = hv;
        }
    }
}

// -------------------------------- launcher ---------------------------------
extern "C" void kernel_launch(void* const* d_in, const int* in_sizes, int n_in,
                              void* d_out, int out_size)
{
    const float* x           = (const float*)d_in[0];
    const float* ln1_g       = (const float*)d_in[1];
    const float* ln1_b       = (const float*)d_in[2];
    const float* w_qkv       = (const float*)d_in[3];
    const float* b_qkv       = (const float*)d_in[4];
    const float* w_attn_proj = (const float*)d_in[5];
    const float* b_attn_proj = (const float*)d_in[6];
    const float* ln2_g       = (const float*)d_in[7];
    const float* ln2_b       = (const float*)d_in[8];
    const float* w_fc        = (const float*)d_in[9];
    const float* b_fc        = (const float*)d_in[10];
    const float* w_mlp_proj  = (const float*)d_in[11];
    const float* b_mlp_proj  = (const float*)d_in[12];
    float* out = (float*)d_out;

    float *X1;
    __half *H16, *QKV16, *ATT16, *FF16, *Wq16, *Wa16, *Wf16, *Wm16;
    cudaGetSymbolAddress((void**)&X1,    g_X1);
    cudaGetSymbolAddress((void**)&H16,   g_H16);
    cudaGetSymbolAddress((void**)&QKV16, g_QKV16);
    cudaGetSymbolAddress((void**)&ATT16, g_ATT16);
    cudaGetSymbolAddress((void**)&FF16,  g_FF16);
    cudaGetSymbolAddress((void**)&Wq16,  g_Wq16);
    cudaGetSymbolAddress((void**)&Wa16,  g_Wa16);
    cudaGetSymbolAddress((void**)&Wf16,  g_Wf16);
    cudaGetSymbolAddress((void**)&Wm16,  g_Wm16);

    cudaFuncSetAttribute(gemm_h<0,1>, cudaFuncAttributeMaxDynamicSharedMemorySize, GEMM_SMEM);
    cudaFuncSetAttribute(gemm_h<1,1>, cudaFuncAttributeMaxDynamicSharedMemorySize, GEMM_SMEM);
    cudaFuncSetAttribute(gemm_h<2,0>, cudaFuncAttributeMaxDynamicSharedMemorySize, GEMM_SMEM);
    cudaFuncSetAttribute(flash_wmma, cudaFuncAttributeMaxDynamicSharedMemorySize, FLASH_SMEM);

    cvt_half_kernel<<<(3*Cdim*Cdim/4 + 255)/256, 256>>>(w_qkv, Wq16, 3*Cdim*Cdim/4);
    cvt_half_kernel<<<(Cdim*Cdim/4 + 255)/256, 256>>>(w_attn_proj, Wa16, Cdim*Cdim/4);
    cvt_half_kernel<<<(Cdim*FFdim/4 + 255)/256, 256>>>(w_fc, Wf16, Cdim*FFdim/4);
    cvt_half_kernel<<<(FFdim*Cdim/4 + 255)/256, 256>>>(w_mlp_proj, Wm16, FFdim*Cdim/4);

    // 1. h = LN1(x)                      (fp16 out)
    ln_kernel<<<Mrows / 8, 256>>>(x, ln1_g, ln1_b, H16);
    // 2. qkv = h @ w_qkv + b             (fp16 out)
    gemm_h<0,1><<<dim3(3 * Cdim / BN, Mrows / BM), 256, GEMM_SMEM>>>(
        H16, Wq16, b_qkv, nullptr, QKV16, Mrows, 3 * Cdim, Cdim);
    // 3. causal flash attention (wmma)   (fp16 out)
    flash_wmma<<<dim3(Tlen / 64, Bsz * NHead), 128, FLASH_SMEM>>>(QKV16, ATT16);
    // 4. x1 = x + attn @ w_attn_proj + b (fp32 out)
    gemm_h<2,0><<<dim3(Cdim / BN, Mrows / BM), 256, GEMM_SMEM>>>(
        ATT16, Wa16, b_attn_proj, x, X1, Mrows, Cdim, Cdim);
    // 5. h = LN2(x1)                     (fp16 out)
    ln_kernel<<<Mrows / 8, 256>>>(X1, ln2_g, ln2_b, H16);
    // 6. ff = gelu(h @ w_fc + b)         (fp16 out)
    gemm_h<1,1><<<dim3(FFdim / BN, Mrows / BM), 256, GEMM_SMEM>>>(
        H16, Wf16, b_fc, nullptr, FF16, Mrows, FFdim, Cdim);
    // 7. out = x1 + ff @ w_mlp_proj + b  (fp32 out)
    gemm_h<2,0><<<dim3(Cdim / BN, Mrows / BM), 256, GEMM_SMEM>>>(
        FF16, Wm16, b_mlp_proj, X1, out, Mrows, Cdim, FFdim);
}

// round 8
// speedup vs baseline: 6.9140x; 1.3873x over previous
#include <cuda_runtime.h>
#include <cuda_fp16.h>
#include <math.h>
#include <stdint.h>
#include <mma.h>

using namespace nvcuda;

// ---------------------------------------------------------------------------
// TransformerBlock B=4,T=2048,C=1024,NH=16,HD=64,FF=4096 fp32.
// R7: GEMMs on raw mma.sync.m16n8k16 + ldmatrix, XOR-swizzled smem,
//     register-direct epilogue. Flash/LN unchanged from R6.
// ---------------------------------------------------------------------------

#define Bsz   4
#define Tlen  2048
#define Cdim  1024
#define NHead 16
#define HDim  64
#define FFdim 4096
#define Mrows (Bsz * Tlen)   // 8192

// ------------------------- scratch (device globals) ------------------------
__device__ float  g_X1 [Mrows * Cdim];
__device__ __half g_H16  [Mrows * Cdim];
__device__ __half g_QKV16[Mrows * 3 * Cdim];
__device__ __half g_ATT16[Mrows * Cdim];
__device__ __half g_FF16 [Mrows * FFdim];
__device__ __half g_Wq16[Cdim * 3 * Cdim];
__device__ __half g_Wa16[Cdim * Cdim];
__device__ __half g_Wf16[Cdim * FFdim];
__device__ __half g_Wm16[FFdim * Cdim];

// --------------------------- fp32 -> fp16 convert --------------------------
__global__ void __launch_bounds__(256)
cvt_half_kernel(const float* __restrict__ in, __half* __restrict__ out, int n4)
{
    int i = blockIdx.x * 256 + threadIdx.x;
    if (i < n4) {
        float4 v = reinterpret_cast<const float4*>(in)[i];
        __half2 h0 = __floats2half2_rn(v.x, v.y);
        __half2 h1 = __floats2half2_rn(v.z, v.w);
        uint2 o = { *(uint32_t*)&h0, *(uint32_t*)&h1 };
        reinterpret_cast<uint2*>(out)[i] = o;
    }
}

// ------------------------ LayerNorm (warp per row) -------------------------
__global__ void __launch_bounds__(256)
ln_kernel(const float* __restrict__ X, const float* __restrict__ g,
          const float* __restrict__ b, __half* __restrict__ Y)
{
    int w    = threadIdx.x >> 5;
    int lane = threadIdx.x & 31;
    int row  = blockIdx.x * 8 + w;

    const float4* xr = reinterpret_cast<const float4*>(X + (size_t)row * Cdim);
    float4 v[8];
    float sum = 0.0f, sq = 0.0f;
#pragma unroll
    for (int i = 0; i < 8; i++) {
        v[i] = xr[lane + 32 * i];
        sum += v[i].x + v[i].y + v[i].z + v[i].w;
        sq  += v[i].x*v[i].x + v[i].y*v[i].y + v[i].z*v[i].z + v[i].w*v[i].w;
    }
#pragma unroll
    for (int st = 16; st > 0; st >>= 1) {
        sum += __shfl_xor_sync(0xFFFFFFFFu, sum, st);
        sq  += __shfl_xor_sync(0xFFFFFFFFu, sq,  st);
    }
    float mu   = sum * (1.0f / Cdim);
    float var  = sq  * (1.0f / Cdim) - mu * mu;
    float rstd = rsqrtf(var + 1e-5f);

    const float4* gr = reinterpret_cast<const float4*>(g);
    const float4* br = reinterpret_cast<const float4*>(b);
    uint2* yr = reinterpret_cast<uint2*>(Y + (size_t)row * Cdim);
#pragma unroll
    for (int i = 0; i < 8; i++) {
        float4 gg = gr[lane + 32 * i];
        float4 bb = br[lane + 32 * i];
        __half2 h0 = __floats2half2_rn((v[i].x - mu) * rstd * gg.x + bb.x,
                                       (v[i].y - mu) * rstd * gg.y + bb.y);
        __half2 h1 = __floats2half2_rn((v[i].z - mu) * rstd * gg.z + bb.z,
                                       (v[i].w - mu) * rstd * gg.w + bb.w);
        uint2 o = { *(uint32_t*)&h0, *(uint32_t*)&h1 };
        yr[lane + 32 * i] = o;
    }
}

// ------------------------------ common helpers -----------------------------
__device__ __forceinline__ float gelu_f(float x)
{
    float x3 = x * x * x;
    float t  = tanhf(0.7978845608028654f * (x + 0.044715f * x3));
    return 0.5f * x * (1.0f + t);
}

#define CP_ASYNC16(dst, src) \
    asm volatile("cp.async.cg.shared.global [%0], [%1], 16;" :: "r"(dst), "l"(src))
#define CP_COMMIT()   asm volatile("cp.async.commit_group;" ::: "memory")
#define CP_WAIT(n)    asm volatile("cp.async.wait_group %0;" :: "n"(n) : "memory")

__device__ __forceinline__ uint32_t smem_u32(const void* p) {
    uint32_t a;
    asm("{ .reg .u64 t; cvta.to.shared.u64 t, %1; cvt.u32.u64 %0, t; }"
        : "=r"(a) : "l"(p));
    return a;
}

__device__ __forceinline__ void ldsm_x4(uint32_t& r0, uint32_t& r1,
                                        uint32_t& r2, uint32_t& r3, uint32_t addr)
{
    asm volatile("ldmatrix.sync.aligned.m8n8.x4.shared.b16 {%0,%1,%2,%3}, [%4];"
        : "=r"(r0), "=r"(r1), "=r"(r2), "=r"(r3) : "r"(addr));
}
__device__ __forceinline__ void ldsm_x4_t(uint32_t& r0, uint32_t& r1,
                                          uint32_t& r2, uint32_t& r3, uint32_t addr)
{
    asm volatile("ldmatrix.sync.aligned.m8n8.x4.trans.shared.b16 {%0,%1,%2,%3}, [%4];"
        : "=r"(r0), "=r"(r1), "=r"(r2), "=r"(r3) : "r"(addr));
}
__device__ __forceinline__ void mma_16816(float* c, const uint32_t* a,
                                          const uint32_t* b)
{
    asm volatile("mma.sync.aligned.m16n8k16.row.col.f32.f16.f16.f32 "
        "{%0,%1,%2,%3}, {%4,%5,%6,%7}, {%8,%9}, {%0,%1,%2,%3};"
        : "+f"(c[0]), "+f"(c[1]), "+f"(c[2]), "+f"(c[3])
        : "r"(a[0]), "r"(a[1]), "r"(a[2]), "r"(a[3]), "r"(b[0]), "r"(b[1]));
}

// --------------------------- raw mma.sync GEMM -----------------------------
// 128x128x64 tiles, 8 warps (2x4), 64x32 warptile, double-buffered, 2 CTA/SM.
// A smem: [128][64]h, 128B rows, chunk^=(row&7) swizzle.
// B smem: [64][128]h, 256B rows, low-3-bit chunk swizzle.
static constexpr int BM = 128, BN = 128, BK = 64;
static constexpr int A_BYTES = BM * BK * 2;        // 16384
static constexpr int B_BYTES = BK * BN * 2;        // 16384
static constexpr int STAGE   = A_BYTES + B_BYTES;  // 32768
static constexpr int GEMM_SMEM = 2 * STAGE;        // 65536

// EPI: 0 none, 1 gelu, 2 +R.  OUTH: 1 fp16 out, 0 fp32 out.
template<int EPI, int OUTH>
__global__ void __launch_bounds__(256, 2)
gemm_mma(const __half* __restrict__ A, const __half* __restrict__ W,
         const float* __restrict__ bias, const float* __restrict__ R,
         void* __restrict__ Cout, int M, int N, int K)
{
    extern __shared__ __align__(128) char smem[];
    uint32_t sA_u[2] = { smem_u32(smem),           smem_u32(smem + STAGE) };
    uint32_t sB_u[2] = { smem_u32(smem + A_BYTES), smem_u32(smem + STAGE + A_BYTES) };

    int tid  = threadIdx.x;
    int wid  = tid >> 5;
    int lane = tid & 31;
    int wm   = wid >> 2;          // 0..1 (64-row slab)
    int wn   = wid & 3;           // 0..3 (32-col slab)
    int m0   = blockIdx.y * BM;
    int n0   = blockIdx.x * BN;

    float acc[4][4][4];           // [mi][ni][reg]
#pragma unroll
    for (int i = 0; i < 4; i++)
#pragma unroll
        for (int j = 0; j < 4; j++)
#pragma unroll
            for (int r = 0; r < 4; r++) acc[i][j][r] = 0.0f;

    int nk = K / BK;

    // cp.async stage loader with swizzled smem destinations
    auto issue_stage = [&](int s, int buf) {
        const __half* Ab = A + (size_t)m0 * K + s * BK;
        const __half* Wb = W + (size_t)s * BK * N + n0;
#pragma unroll
        for (int i = 0; i < 4; i++) {
            int f = tid + i * 256;
            int ra = f >> 3, ca = f & 7;          // A: 128 rows x 8 chunks
            uint32_t da = sA_u[buf] + (uint32_t)((ra * 8 + (ca ^ (ra & 7))) * 16);
            CP_ASYNC16(da, Ab + (size_t)ra * K + ca * 8);
            int rb = f >> 4, cb = f & 15;         // B: 64 rows x 16 chunks
            int pb = (cb & 8) | ((cb & 7) ^ (rb & 7));
            uint32_t db = sB_u[buf] + (uint32_t)((rb * 16 + pb) * 16);
            CP_ASYNC16(db, Wb + (size_t)rb * N + cb * 8);
        }
        CP_COMMIT();
    };

    issue_stage(0, 0);

    // per-lane ldmatrix address components
    int l15 = lane & 15;
    int hi  = lane >> 4;          // 0/1
    int x   = lane & 7;           // swizzle xor (row&7 == lane&7 here)

    for (int s = 0; s < nk; ++s) {
        int buf = s & 1;
        if (s + 1 < nk) {
            issue_stage(s + 1, buf ^ 1);
            CP_WAIT(1);
        } else {
            CP_WAIT(0);
        }
        __syncthreads();

        uint32_t aT = sA_u[buf];
        uint32_t bT = sB_u[buf];
#pragma unroll
        for (int ks = 0; ks < 4; ++ks) {
            // A fragments: 4 x m16k16
            uint32_t a[4][4];
#pragma unroll
            for (int mi = 0; mi < 4; mi++) {
                int row = wm * 64 + mi * 16 + l15;
                int ch  = (ks * 2 + hi) ^ x;
                ldsm_x4(a[mi][0], a[mi][1], a[mi][2], a[mi][3],
                        aT + (uint32_t)((row * 8 + ch) * 16));
            }
            // B fragments: 2 x (k16 x n16) -> 4 n8 frags
            uint32_t b[4][2];
#pragma unroll
            for (int nj = 0; nj < 2; nj++) {
                int row = ks * 16 + l15;
                int cl  = wn * 4 + nj * 2 + hi;
                int ch  = (cl & 8) | ((cl & 7) ^ x);
                uint32_t r0, r1, r2, r3;
                ldsm_x4_t(r0, r1, r2, r3, bT + (uint32_t)((row * 16 + ch) * 16));
                b[nj * 2][0] = r0; b[nj * 2][1] = r1;
                b[nj * 2 + 1][0] = r2; b[nj * 2 + 1][1] = r3;
            }
#pragma unroll
            for (int mi = 0; mi < 4; mi++)
#pragma unroll
                for (int ni = 0; ni < 4; ni++)
                    mma_16816(acc[mi][ni], a[mi], b[ni]);
        }
        __syncthreads();
    }

    // ---- register-direct epilogue ----
    int rbase = m0 + wm * 64 + (lane >> 2);
    int cbase = n0 + wn * 32 + (lane & 3) * 2;
#pragma unroll
    for (int mi = 0; mi < 4; mi++) {
#pragma unroll
        for (int ni = 0; ni < 4; ni++) {
            int col = cbase + ni * 8;
            float2 bi = *reinterpret_cast<const float2*>(bias + col);
#pragma unroll
            for (int h = 0; h < 2; h++) {      // h=0: row, h=1: row+8
                int row = rbase + mi * 16 + h * 8;
                float v0 = acc[mi][ni][h * 2 + 0] + bi.x;
                float v1 = acc[mi][ni][h * 2 + 1] + bi.y;
                if (EPI == 1) { v0 = gelu_f(v0); v1 = gelu_f(v1); }
                if (EPI == 2) {
                    float2 rr = *reinterpret_cast<const float2*>(
                        R + (size_t)row * N + col);
                    v0 += rr.x; v1 += rr.y;
                }
                if (OUTH) {
                    __half2 hv = __floats2half2_rn(v0, v1);
                    *reinterpret_cast<__half2*>(
                        (__half*)Cout + (size_t)row * N + col) = hv;
                } else {
                    float2 fv = { v0, v1 };
                    *reinterpret_cast<float2*>(
                        (float*)Cout + (size_t)row * N + col) = fv;
                }
            }
        }
    }
}

// ------------------------- wmma fp16 flash attention -----------------------
static constexpr int LQ = 72;
static constexpr int LS = 68;
static constexpr int Q_OFF  = 0;
static constexpr int K_OFF0 = Q_OFF  + 64 * LQ * 2;
static constexpr int V_OFF0 = K_OFF0 + 64 * LQ * 2;
static constexpr int K_OFF1 = V_OFF0 + 64 * LQ * 2;
static constexpr int V_OFF1 = K_OFF1 + 64 * LQ * 2;
static constexpr int P_OFF  = V_OFF1 + 64 * LQ * 2;
static constexpr int S_OFF  = P_OFF  + 64 * LQ * 2;
static constexpr int O_OFF  = S_OFF  + 64 * LS * 4;
static constexpr int M_OFF  = O_OFF  + 64 * LS * 4;
static constexpr int L_OFF  = M_OFF  + 64 * 4;
static constexpr int FLASH_SMEM = L_OFF + 64 * 4;

__global__ void __launch_bounds__(128, 2)
flash_wmma(const __half* __restrict__ QKV, __half* __restrict__ ATT)
{
    extern __shared__ __align__(128) char smem[];
    __half* Qs = (__half*)(smem + Q_OFF);
    __half* Ks[2] = { (__half*)(smem + K_OFF0), (__half*)(smem + K_OFF1) };
    __half* Vs[2] = { (__half*)(smem + V_OFF0), (__half*)(smem + V_OFF1) };
    __half* Ps = (__half*)(smem + P_OFF);
    float*  Ss = (float*)(smem + S_OFF);
    float*  Os = (float*)(smem + O_OFF);
    float*  mrow = (float*)(smem + M_OFF);
    float*  lrow = (float*)(smem + L_OFF);
    uint32_t Qu = smem_u32(Qs);
    uint32_t Ku[2] = { smem_u32(Ks[0]), smem_u32(Ks[1]) };
    uint32_t Vu[2] = { smem_u32(Vs[0]), smem_u32(Vs[1]) };

    int tid  = threadIdx.x;
    int w    = tid >> 5;
    int lane = tid & 31;
    int qt   = gridDim.x - 1 - blockIdx.x;
    int bh   = blockIdx.y;
    int b    = bh >> 4;
    int h    = bh & 15;
    int q0   = qt * 64;

    for (int i = tid; i < 64 * LS; i += 128) Os[i] = 0.0f;
    if (tid < 64) { mrow[tid] = -1e30f; lrow[tid] = 0.0f; }

    auto issue_kv = [&](int j0, int buf) {
        const __half* Kg = QKV + (size_t)(b * Tlen + j0) * (3 * Cdim) + Cdim + h * HDim;
        const __half* Vg = Kg + Cdim;
#pragma unroll
        for (int i = 0; i < 4; i++) {
            int f = tid + i * 128;
            int r = f >> 3, c8 = f & 7;
            CP_ASYNC16(Ku[buf] + (r * LQ + c8 * 8) * 2, Kg + (size_t)r * (3 * Cdim) + c8 * 8);
            CP_ASYNC16(Vu[buf] + (r * LQ + c8 * 8) * 2, Vg + (size_t)r * (3 * Cdim) + c8 * 8);
        }
        CP_COMMIT();
    };

    {
        const __half* Qg = QKV + (size_t)(b * Tlen + q0) * (3 * Cdim) + h * HDim;
#pragma unroll
        for (int i = 0; i < 4; i++) {
            int f = tid + i * 128;
            int r = f >> 3, c8 = f & 7;
            CP_ASYNC16(Qu + (r * LQ + c8 * 8) * 2, Qg + (size_t)r * (3 * Cdim) + c8 * 8);
        }
        CP_COMMIT();
        issue_kv(0, 0);
    }

    int srow_q = w * 16 + (lane >> 1);
    int half   = lane & 1;
    int qrow_g = q0 + srow_q;

    for (int j0 = 0; j0 <= q0; j0 += 64) {
        int buf = (j0 >> 6) & 1;
        if (j0 + 64 <= q0) {
            issue_kv(j0 + 64, buf ^ 1);
            CP_WAIT(1);
        } else {
            CP_WAIT(0);
        }
        __syncthreads();

        {
            wmma::fragment<wmma::matrix_a, 16, 16, 16, __half, wmma::row_major> fa[4];
#pragma unroll
            for (int ks = 0; ks < 4; ks++)
                wmma::load_matrix_sync(fa[ks], Qs + (w * 16) * LQ + ks * 16, LQ);
#pragma unroll
            for (int n = 0; n < 4; n++) {
                wmma::fragment<wmma::accumulator, 16, 16, 16, float> accS;
                wmma::fill_fragment(accS, 0.0f);
#pragma unroll
                for (int ks = 0; ks < 4; ks++) {
                    wmma::fragment<wmma::matrix_b, 16, 16, 16, __half, wmma::col_major> fb;
                    wmma::load_matrix_sync(fb, Ks[buf] + (n * 16) * LQ + ks * 16, LQ);
                    wmma::mma_sync(accS, fa[ks], fb, accS);
                }
                wmma::store_matrix_sync(Ss + (w * 16) * LS + n * 16, accS, LS,
                                        wmma::mem_row_major);
            }
        }
        __syncthreads();

        {
            float* sr = Ss + srow_q * LS + half * 32;
            bool diag = (j0 == q0);
            float sv[32];
            float tmax = -1e30f;
#pragma unroll
            for (int c = 0; c < 32; c++) {
                float s = sr[c] * 0.125f;
                if (diag && (j0 + half * 32 + c > qrow_g)) s = -1e30f;
                sv[c] = s;
                tmax = fmaxf(tmax, s);
            }
            tmax = fmaxf(tmax, __shfl_xor_sync(0xFFFFFFFFu, tmax, 1));
            float m_old = mrow[srow_q];
            float m_new = fmaxf(m_old, tmax);
            float scale = __expf(m_old - m_new);
            float sum = 0.0f;
            __half* pr = Ps + srow_q * LQ + half * 32;
#pragma unroll
            for (int c = 0; c < 32; c += 2) {
                float p0 = __expf(sv[c]   - m_new);
                float p1 = __expf(sv[c+1] - m_new);
                sum += p0 + p1;
                __half2 hp = __floats2half2_rn(p0, p1);
                *reinterpret_cast<__half2*>(pr + c) = hp;
            }
            sum += __shfl_xor_sync(0xFFFFFFFFu, sum, 1);
            if (half == 0) {
                mrow[srow_q] = m_new;
                lrow[srow_q] = lrow[srow_q] * scale + sum;
            }
            float* orow = Os + srow_q * LS + half * 32;
#pragma unroll
            for (int c = 0; c < 32; c++) orow[c] *= scale;
        }
        __syncthreads();

        {
            wmma::fragment<wmma::matrix_a, 16, 16, 16, __half, wmma::row_major> fp[4];
#pragma unroll
            for (int ks = 0; ks < 4; ks++)
                wmma::load_matrix_sync(fp[ks], Ps + (w * 16) * LQ + ks * 16, LQ);
#pragma unroll
            for (int n = 0; n < 4; n++) {
                wmma::fragment<wmma::accumulator, 16, 16, 16, float> accO;
                wmma::load_matrix_sync(accO, Os + (w * 16) * LS + n * 16, LS,
                                       wmma::mem_row_major);
#pragma unroll
                for (int ks = 0; ks < 4; ks++) {
                    wmma::fragment<wmma::matrix_b, 16, 16, 16, __half, wmma::row_major> fv;
                    wmma::load_matrix_sync(fv, Vs[buf] + (ks * 16) * LQ + n * 16, LQ);
                    wmma::mma_sync(accO, fp[ks], fv, accO);
                }
                wmma::store_matrix_sync(Os + (w * 16) * LS + n * 16, accO, LS,
                                        wmma::mem_row_major);
            }
        }
        __syncthreads();
    }

    {
        float inv = 1.0f / lrow[srow_q];
        const float* orow = Os + srow_q * LS + half * 32;
        __half* out = ATT + (size_t)(b * Tlen + qrow_g) * Cdim + h * HDim + half * 32;
#pragma unroll
        for (int c = 0; c < 32; c += 2) {
            __half2 hv = __floats2half2_rn(orow[c] * inv, orow[c + 1] * inv);
            *reinterpret_cast<__half2*>(out + c) = hv;
        }
    }
}

// -------------------------------- launcher ---------------------------------
extern "C" void kernel_launch(void* const* d_in, const int* in_sizes, int n_in,
                              void* d_out, int out_size)
{
    const float* x           = (const float*)d_in[0];
    const float* ln1_g       = (const float*)d_in[1];
    const float* ln1_b       = (const float*)d_in[2];
    const float* w_qkv       = (const float*)d_in[3];
    const float* b_qkv       = (const float*)d_in[4];
    const float* w_attn_proj = (const float*)d_in[5];
    const float* b_attn_proj = (const float*)d_in[6];
    const float* ln2_g       = (const float*)d_in[7];
    const float* ln2_b       = (const float*)d_in[8];
    const float* w_fc        = (const float*)d_in[9];
    const float* b_fc        = (const float*)d_in[10];
    const float* w_mlp_proj  = (const float*)d_in[11];
    const float* b_mlp_proj  = (const float*)d_in[12];
    float* out = (float*)d_out;

    float *X1;
    __half *H16, *QKV16, *ATT16, *FF16, *Wq16, *Wa16, *Wf16, *Wm16;
    cudaGetSymbolAddress((void**)&X1,    g_X1);
    cudaGetSymbolAddress((void**)&H16,   g_H16);
    cudaGetSymbolAddress((void**)&QKV16, g_QKV16);
    cudaGetSymbolAddress((void**)&ATT16, g_ATT16);
    cudaGetSymbolAddress((void**)&FF16,  g_FF16);
    cudaGetSymbolAddress((void**)&Wq16,  g_Wq16);
    cudaGetSymbolAddress((void**)&Wa16,  g_Wa16);
    cudaGetSymbolAddress((void**)&Wf16,  g_Wf16);
    cudaGetSymbolAddress((void**)&Wm16,  g_Wm16);

    cudaFuncSetAttribute(gemm_mma<0,1>, cudaFuncAttributeMaxDynamicSharedMemorySize, GEMM_SMEM);
    cudaFuncSetAttribute(gemm_mma<1,1>, cudaFuncAttributeMaxDynamicSharedMemorySize, GEMM_SMEM);
    cudaFuncSetAttribute(gemm_mma<2,0>, cudaFuncAttributeMaxDynamicSharedMemorySize, GEMM_SMEM);
    cudaFuncSetAttribute(flash_wmma, cudaFuncAttributeMaxDynamicSharedMemorySize, FLASH_SMEM);

    cvt_half_kernel<<<(3*Cdim*Cdim/4 + 255)/256, 256>>>(w_qkv, Wq16, 3*Cdim*Cdim/4);
    cvt_half_kernel<<<(Cdim*Cdim/4 + 255)/256, 256>>>(w_attn_proj, Wa16, Cdim*Cdim/4);
    cvt_half_kernel<<<(Cdim*FFdim/4 + 255)/256, 256>>>(w_fc, Wf16, Cdim*FFdim/4);
    cvt_half_kernel<<<(FFdim*Cdim/4 + 255)/256, 256>>>(w_mlp_proj, Wm16, FFdim*Cdim/4);

    // 1. h = LN1(x)                      (fp16 out)
    ln_kernel<<<Mrows / 8, 256>>>(x, ln1_g, ln1_b, H16);
    // 2. qkv = h @ w_qkv + b             (fp16 out)
    gemm_mma<0,1><<<dim3(3 * Cdim / BN, Mrows / BM), 256, GEMM_SMEM>>>(
        H16, Wq16, b_qkv, nullptr, QKV16, Mrows, 3 * Cdim, Cdim);
    // 3. causal flash attention (wmma)   (fp16 out)
    flash_wmma<<<dim3(Tlen / 64, Bsz * NHead), 128, FLASH_SMEM>>>(QKV16, ATT16);
    // 4. x1 = x + attn @ w_attn_proj + b (fp32 out)
    gemm_mma<2,0><<<dim3(Cdim / BN, Mrows / BM), 256, GEMM_SMEM>>>(
        ATT16, Wa16, b_attn_proj, x, X1, Mrows, Cdim, Cdim);
    // 5. h = LN2(x1)                     (fp16 out)
    ln_kernel<<<Mrows / 8, 256>>>(X1, ln2_g, ln2_b, H16);
    // 6. ff = gelu(h @ w_fc + b)         (fp16 out)
    gemm_mma<1,1><<<dim3(FFdim / BN, Mrows / BM), 256, GEMM_SMEM>>>(
        H16, Wf16, b_fc, nullptr, FF16, Mrows, FFdim, Cdim);
    // 7. out = x1 + ff @ w_mlp_proj + b  (fp32 out)
    gemm_mma<2,0><<<dim3(Cdim / BN, Mrows / BM), 256, GEMM_SMEM>>>(
        FF16, Wm16, b_mlp_proj, X1, out, Mrows, Cdim, FFdim);
}

// round 9
// speedup vs baseline: 9.4738x; 1.3702x over previous
#include <cuda_runtime.h>
#include <cuda_fp16.h>
#include <math.h>
#include <stdint.h>

// ---------------------------------------------------------------------------
// TransformerBlock B=4,T=2048,C=1024,NH=16,HD=64,FF=4096 fp32.
// R8: raw mma.sync GEMMs (R7) + raw mma.sync register-resident flash attn.
// ---------------------------------------------------------------------------

#define Bsz   4
#define Tlen  2048
#define Cdim  1024
#define NHead 16
#define HDim  64
#define FFdim 4096
#define Mrows (Bsz * Tlen)   // 8192

// ------------------------- scratch (device globals) ------------------------
__device__ float  g_X1 [Mrows * Cdim];
__device__ __half g_H16  [Mrows * Cdim];
__device__ __half g_QKV16[Mrows * 3 * Cdim];
__device__ __half g_ATT16[Mrows * Cdim];
__device__ __half g_FF16 [Mrows * FFdim];
__device__ __half g_Wq16[Cdim * 3 * Cdim];
__device__ __half g_Wa16[Cdim * Cdim];
__device__ __half g_Wf16[Cdim * FFdim];
__device__ __half g_Wm16[FFdim * Cdim];

// --------------------------- fp32 -> fp16 convert --------------------------
__global__ void __launch_bounds__(256)
cvt_half_kernel(const float* __restrict__ in, __half* __restrict__ out, int n4)
{
    int i = blockIdx.x * 256 + threadIdx.x;
    if (i < n4) {
        float4 v = reinterpret_cast<const float4*>(in)[i];
        __half2 h0 = __floats2half2_rn(v.x, v.y);
        __half2 h1 = __floats2half2_rn(v.z, v.w);
        uint2 o = { *(uint32_t*)&h0, *(uint32_t*)&h1 };
        reinterpret_cast<uint2*>(out)[i] = o;
    }
}

// ------------------------ LayerNorm (warp per row) -------------------------
__global__ void __launch_bounds__(256)
ln_kernel(const float* __restrict__ X, const float* __restrict__ g,
          const float* __restrict__ b, __half* __restrict__ Y)
{
    int w    = threadIdx.x >> 5;
    int lane = threadIdx.x & 31;
    int row  = blockIdx.x * 8 + w;

    const float4* xr = reinterpret_cast<const float4*>(X + (size_t)row * Cdim);
    float4 v[8];
    float sum = 0.0f, sq = 0.0f;
#pragma unroll
    for (int i = 0; i < 8; i++) {
        v[i] = xr[lane + 32 * i];
        sum += v[i].x + v[i].y + v[i].z + v[i].w;
        sq  += v[i].x*v[i].x + v[i].y*v[i].y + v[i].z*v[i].z + v[i].w*v[i].w;
    }
#pragma unroll
    for (int st = 16; st > 0; st >>= 1) {
        sum += __shfl_xor_sync(0xFFFFFFFFu, sum, st);
        sq  += __shfl_xor_sync(0xFFFFFFFFu, sq,  st);
    }
    float mu   = sum * (1.0f / Cdim);
    float var  = sq  * (1.0f / Cdim) - mu * mu;
    float rstd = rsqrtf(var + 1e-5f);

    const float4* gr = reinterpret_cast<const float4*>(g);
    const float4* br = reinterpret_cast<const float4*>(b);
    uint2* yr = reinterpret_cast<uint2*>(Y + (size_t)row * Cdim);
#pragma unroll
    for (int i = 0; i < 8; i++) {
        float4 gg = gr[lane + 32 * i];
        float4 bb = br[lane + 32 * i];
        __half2 h0 = __floats2half2_rn((v[i].x - mu) * rstd * gg.x + bb.x,
                                       (v[i].y - mu) * rstd * gg.y + bb.y);
        __half2 h1 = __floats2half2_rn((v[i].z - mu) * rstd * gg.z + bb.z,
                                       (v[i].w - mu) * rstd * gg.w + bb.w);
        uint2 o = { *(uint32_t*)&h0, *(uint32_t*)&h1 };
        yr[lane + 32 * i] = o;
    }
}

// ------------------------------ common helpers -----------------------------
__device__ __forceinline__ float gelu_f(float x)
{
    float x3 = x * x * x;
    float t  = tanhf(0.7978845608028654f * (x + 0.044715f * x3));
    return 0.5f * x * (1.0f + t);
}

#define CP_ASYNC16(dst, src) \
    asm volatile("cp.async.cg.shared.global [%0], [%1], 16;" :: "r"(dst), "l"(src))
#define CP_COMMIT()   asm volatile("cp.async.commit_group;" ::: "memory")
#define CP_WAIT(n)    asm volatile("cp.async.wait_group %0;" :: "n"(n) : "memory")

__device__ __forceinline__ uint32_t smem_u32(const void* p) {
    uint32_t a;
    asm("{ .reg .u64 t; cvta.to.shared.u64 t, %1; cvt.u32.u64 %0, t; }"
        : "=r"(a) : "l"(p));
    return a;
}

__device__ __forceinline__ void ldsm_x4(uint32_t& r0, uint32_t& r1,
                                        uint32_t& r2, uint32_t& r3, uint32_t addr)
{
    asm volatile("ldmatrix.sync.aligned.m8n8.x4.shared.b16 {%0,%1,%2,%3}, [%4];"
        : "=r"(r0), "=r"(r1), "=r"(r2), "=r"(r3) : "r"(addr));
}
__device__ __forceinline__ void ldsm_x4_t(uint32_t& r0, uint32_t& r1,
                                          uint32_t& r2, uint32_t& r3, uint32_t addr)
{
    asm volatile("ldmatrix.sync.aligned.m8n8.x4.trans.shared.b16 {%0,%1,%2,%3}, [%4];"
        : "=r"(r0), "=r"(r1), "=r"(r2), "=r"(r3) : "r"(addr));
}
__device__ __forceinline__ void mma_16816(float* c, const uint32_t* a,
                                          const uint32_t* b)
{
    asm volatile("mma.sync.aligned.m16n8k16.row.col.f32.f16.f16.f32 "
        "{%0,%1,%2,%3}, {%4,%5,%6,%7}, {%8,%9}, {%0,%1,%2,%3};"
        : "+f"(c[0]), "+f"(c[1]), "+f"(c[2]), "+f"(c[3])
        : "r"(a[0]), "r"(a[1]), "r"(a[2]), "r"(a[3]), "r"(b[0]), "r"(b[1]));
}

// --------------------------- raw mma.sync GEMM (R7) ------------------------
static constexpr int BM = 128, BN = 128, BK = 64;
static constexpr int A_BYTES = BM * BK * 2;
static constexpr int B_BYTES = BK * BN * 2;
static constexpr int STAGE   = A_BYTES + B_BYTES;
static constexpr int GEMM_SMEM = 2 * STAGE;        // 65536

template<int EPI, int OUTH>
__global__ void __launch_bounds__(256, 2)
gemm_mma(const __half* __restrict__ A, const __half* __restrict__ W,
         const float* __restrict__ bias, const float* __restrict__ R,
         void* __restrict__ Cout, int M, int N, int K)
{
    extern __shared__ __align__(128) char smem[];
    uint32_t sA_u[2] = { smem_u32(smem),           smem_u32(smem + STAGE) };
    uint32_t sB_u[2] = { smem_u32(smem + A_BYTES), smem_u32(smem + STAGE + A_BYTES) };

    int tid  = threadIdx.x;
    int wid  = tid >> 5;
    int lane = tid & 31;
    int wm   = wid >> 2;
    int wn   = wid & 3;
    int m0   = blockIdx.y * BM;
    int n0   = blockIdx.x * BN;

    float acc[4][4][4];
#pragma unroll
    for (int i = 0; i < 4; i++)
#pragma unroll
        for (int j = 0; j < 4; j++)
#pragma unroll
            for (int r = 0; r < 4; r++) acc[i][j][r] = 0.0f;

    int nk = K / BK;

    auto issue_stage = [&](int s, int buf) {
        const __half* Ab = A + (size_t)m0 * K + s * BK;
        const __half* Wb = W + (size_t)s * BK * N + n0;
#pragma unroll
        for (int i = 0; i < 4; i++) {
            int f = tid + i * 256;
            int ra = f >> 3, ca = f & 7;
            uint32_t da = sA_u[buf] + (uint32_t)((ra * 8 + (ca ^ (ra & 7))) * 16);
            CP_ASYNC16(da, Ab + (size_t)ra * K + ca * 8);
            int rb = f >> 4, cb = f & 15;
            int pb = (cb & 8) | ((cb & 7) ^ (rb & 7));
            uint32_t db = sB_u[buf] + (uint32_t)((rb * 16 + pb) * 16);
            CP_ASYNC16(db, Wb + (size_t)rb * N + cb * 8);
        }
        CP_COMMIT();
    };

    issue_stage(0, 0);

    int l15 = lane & 15;
    int hi  = lane >> 4;
    int x   = lane & 7;

    for (int s = 0; s < nk; ++s) {
        int buf = s & 1;
        if (s + 1 < nk) {
            issue_stage(s + 1, buf ^ 1);
            CP_WAIT(1);
        } else {
            CP_WAIT(0);
        }
        __syncthreads();

        uint32_t aT = sA_u[buf];
        uint32_t bT = sB_u[buf];
#pragma unroll
        for (int ks = 0; ks < 4; ++ks) {
            uint32_t a[4][4];
#pragma unroll
            for (int mi = 0; mi < 4; mi++) {
                int row = wm * 64 + mi * 16 + l15;
                int ch  = (ks * 2 + hi) ^ x;
                ldsm_x4(a[mi][0], a[mi][1], a[mi][2], a[mi][3],
                        aT + (uint32_t)((row * 8 + ch) * 16));
            }
            uint32_t b[4][2];
#pragma unroll
            for (int nj = 0; nj < 2; nj++) {
                int row = ks * 16 + l15;
                int cl  = wn * 4 + nj * 2 + hi;
                int ch  = (cl & 8) | ((cl & 7) ^ x);
                uint32_t r0, r1, r2, r3;
                ldsm_x4_t(r0, r1, r2, r3, bT + (uint32_t)((row * 16 + ch) * 16));
                b[nj * 2][0] = r0; b[nj * 2][1] = r1;
                b[nj * 2 + 1][0] = r2; b[nj * 2 + 1][1] = r3;
            }
#pragma unroll
            for (int mi = 0; mi < 4; mi++)
#pragma unroll
                for (int ni = 0; ni < 4; ni++)
                    mma_16816(acc[mi][ni], a[mi], b[ni]);
        }
        __syncthreads();
    }

    int rbase = m0 + wm * 64 + (lane >> 2);
    int cbase = n0 + wn * 32 + (lane & 3) * 2;
#pragma unroll
    for (int mi = 0; mi < 4; mi++) {
#pragma unroll
        for (int ni = 0; ni < 4; ni++) {
            int col = cbase + ni * 8;
            float2 bi = *reinterpret_cast<const float2*>(bias + col);
#pragma unroll
            for (int h = 0; h < 2; h++) {
                int row = rbase + mi * 16 + h * 8;
                float v0 = acc[mi][ni][h * 2 + 0] + bi.x;
                float v1 = acc[mi][ni][h * 2 + 1] + bi.y;
                if (EPI == 1) { v0 = gelu_f(v0); v1 = gelu_f(v1); }
                if (EPI == 2) {
                    float2 rr = *reinterpret_cast<const float2*>(
                        R + (size_t)row * N + col);
                    v0 += rr.x; v1 += rr.y;
                }
                if (OUTH) {
                    __half2 hv = __floats2half2_rn(v0, v1);
                    *reinterpret_cast<__half2*>(
                        (__half*)Cout + (size_t)row * N + col) = hv;
                } else {
                    float2 fv = { v0, v1 };
                    *reinterpret_cast<float2*>(
                        (float*)Cout + (size_t)row * N + col) = fv;
                }
            }
        }
    }
}

// ---------------- raw mma.sync register-resident flash attention -----------
// 128 threads (4 warps), 64 q rows/block (16 per warp), KV tiles 64,
// double-buffered. Q/K/V in swizzled smem; S, P, O, softmax state in regs.
static constexpr int FLASH_SMEM = 5 * 8192;   // Q + 2*(K,V)

__global__ void __launch_bounds__(128, 2)
flash_mma(const __half* __restrict__ QKV, __half* __restrict__ ATT)
{
    extern __shared__ __align__(128) char smem[];
    uint32_t Qu = smem_u32(smem);
    uint32_t Ku[2] = { Qu + 8192,  Qu + 24576 };
    uint32_t Vu[2] = { Qu + 16384, Qu + 32768 };

    int tid  = threadIdx.x;
    int w    = tid >> 5;
    int lane = tid & 31;
    int qt   = gridDim.x - 1 - blockIdx.x;      // heavy tiles first
    int bh   = blockIdx.y;
    int b    = bh >> 4;
    int h    = bh & 15;
    int q0   = qt * 64;

    // 64x64 fp16 tile loader (src row stride 3C), swizzled dst
    auto ld_tile = [&](uint32_t dstu, const __half* src) {
#pragma unroll
        for (int i = 0; i < 4; i++) {
            int f = tid + i * 128;
            int r = f >> 3, c = f & 7;
            uint32_t d = dstu + (uint32_t)((r * 8 + (c ^ (r & 7))) * 16);
            CP_ASYNC16(d, src + (size_t)r * (3 * Cdim) + c * 8);
        }
    };

    const __half* Qg  = QKV + (size_t)(b * Tlen + q0) * (3 * Cdim) + h * HDim;
    const __half* Kg0 = QKV + (size_t)(b * Tlen) * (3 * Cdim) + Cdim + h * HDim;
    ld_tile(Qu, Qg);
    CP_COMMIT();
    ld_tile(Ku[0], Kg0);
    ld_tile(Vu[0], Kg0 + Cdim);
    CP_COMMIT();

    // Q fragments (A-layout), scaled by 1/sqrt(64)
    uint32_t qa[4][4];
    {
        CP_WAIT(1);              // Q group done
        __syncthreads();
        int l15 = lane & 15, hi = lane >> 4;
        int row = w * 16 + l15;
#pragma unroll
        for (int dk = 0; dk < 4; dk++) {
            int ch = (dk * 2 + hi) ^ (row & 7);
            ldsm_x4(qa[dk][0], qa[dk][1], qa[dk][2], qa[dk][3],
                    Qu + (uint32_t)((row * 8 + ch) * 16));
        }
        __half2 sc = __floats2half2_rn(0.125f, 0.125f);
#pragma unroll
        for (int dk = 0; dk < 4; dk++)
#pragma unroll
            for (int r = 0; r < 4; r++) {
                __half2 v = *reinterpret_cast<__half2*>(&qa[dk][r]);
                v = __hmul2(v, sc);
                qa[dk][r] = *reinterpret_cast<uint32_t*>(&v);
            }
    }

    float o[8][4];
#pragma unroll
    for (int n = 0; n < 8; n++)
#pragma unroll
        for (int r = 0; r < 4; r++) o[n][r] = 0.0f;
    float m0 = -1e30f, m1 = -1e30f, l0 = 0.0f, l1 = 0.0f;

    int g   = lane >> 3;        // ldsm address group
    int r8  = lane & 7;
    int l15 = lane & 15;
    int hi  = lane >> 4;
    int qr  = q0 + w * 16 + (lane >> 2);   // row for c0/c1; +8 for c2/c3
    int nt  = q0 >> 6;

    for (int t = 0; t <= nt; ++t) {
        int buf = t & 1;
        if (t < nt) {
            const __half* Kg = QKV + (size_t)(b * Tlen + (t + 1) * 64) * (3 * Cdim)
                             + Cdim + h * HDim;
            ld_tile(Ku[buf ^ 1], Kg);
            ld_tile(Vu[buf ^ 1], Kg + Cdim);
            CP_COMMIT();
            CP_WAIT(1);
        } else {
            CP_WAIT(0);
        }
        __syncthreads();

        // ---- S = Q @ K^T  (registers) ----
        float s[8][4];
#pragma unroll
        for (int n = 0; n < 8; n++)
#pragma unroll
            for (int r = 0; r < 4; r++) s[n][r] = 0.0f;
#pragma unroll
        for (int dk = 0; dk < 4; dk++) {
            uint32_t kb[8][2];
#pragma unroll
            for (int p = 0; p < 4; p++) {
                int row = p * 16 + (g >> 1) * 8 + r8;
                int ch  = (dk * 2 + (g & 1)) ^ (row & 7);
                uint32_t r0, r1, r2, r3;
                ldsm_x4(r0, r1, r2, r3, Ku[buf] + (uint32_t)((row * 8 + ch) * 16));
                kb[2*p][0] = r0; kb[2*p][1] = r1;
                kb[2*p+1][0] = r2; kb[2*p+1][1] = r3;
            }
#pragma unroll
            for (int n = 0; n < 8; n++) mma_16816(s[n], qa[dk], kb[n]);
        }

        // ---- online softmax in registers ----
        bool diag = (t == nt);
        float mx0 = -1e30f, mx1 = -1e30f;
#pragma unroll
        for (int n = 0; n < 8; n++) {
            if (diag) {
                int col = t * 64 + n * 8 + (lane & 3) * 2;
                if (col     > qr)     s[n][0] = -1e30f;
                if (col + 1 > qr)     s[n][1] = -1e30f;
                if (col     > qr + 8) s[n][2] = -1e30f;
                if (col + 1 > qr + 8) s[n][3] = -1e30f;
            }
            mx0 = fmaxf(mx0, fmaxf(s[n][0], s[n][1]));
            mx1 = fmaxf(mx1, fmaxf(s[n][2], s[n][3]));
        }
        mx0 = fmaxf(mx0, __shfl_xor_sync(0xFFFFFFFFu, mx0, 1));
        mx0 = fmaxf(mx0, __shfl_xor_sync(0xFFFFFFFFu, mx0, 2));
        mx1 = fmaxf(mx1, __shfl_xor_sync(0xFFFFFFFFu, mx1, 1));
        mx1 = fmaxf(mx1, __shfl_xor_sync(0xFFFFFFFFu, mx1, 2));

        float mn0 = fmaxf(m0, mx0), mn1 = fmaxf(m1, mx1);
        float sc0 = __expf(m0 - mn0), sc1 = __expf(m1 - mn1);
        float sum0 = 0.0f, sum1 = 0.0f;
        uint32_t pa[4][4];
#pragma unroll
        for (int dk = 0; dk < 4; dk++) {
            float e00 = __expf(s[2*dk][0]   - mn0);
            float e01 = __expf(s[2*dk][1]   - mn0);
            float e02 = __expf(s[2*dk][2]   - mn1);
            float e03 = __expf(s[2*dk][3]   - mn1);
            float e10 = __expf(s[2*dk+1][0] - mn0);
            float e11 = __expf(s[2*dk+1][1] - mn0);
            float e12 = __expf(s[2*dk+1][2] - mn1);
            float e13 = __expf(s[2*dk+1][3] - mn1);
            sum0 += e00 + e01 + e10 + e11;
            sum1 += e02 + e03 + e12 + e13;
            __half2 h0 = __floats2half2_rn(e00, e01);
            __half2 h1 = __floats2half2_rn(e02, e03);
            __half2 h2 = __floats2half2_rn(e10, e11);
            __half2 h3 = __floats2half2_rn(e12, e13);
            pa[dk][0] = *reinterpret_cast<uint32_t*>(&h0);
            pa[dk][1] = *reinterpret_cast<uint32_t*>(&h1);
            pa[dk][2] = *reinterpret_cast<uint32_t*>(&h2);
            pa[dk][3] = *reinterpret_cast<uint32_t*>(&h3);
        }
        sum0 += __shfl_xor_sync(0xFFFFFFFFu, sum0, 1);
        sum0 += __shfl_xor_sync(0xFFFFFFFFu, sum0, 2);
        sum1 += __shfl_xor_sync(0xFFFFFFFFu, sum1, 1);
        sum1 += __shfl_xor_sync(0xFFFFFFFFu, sum1, 2);
        l0 = l0 * sc0 + sum0;
        l1 = l1 * sc1 + sum1;
        m0 = mn0; m1 = mn1;
#pragma unroll
        for (int n = 0; n < 8; n++) {
            o[n][0] *= sc0; o[n][1] *= sc0;
            o[n][2] *= sc1; o[n][3] *= sc1;
        }

        // ---- O += P @ V ----
#pragma unroll
        for (int dk = 0; dk < 4; dk++) {
            uint32_t vb[8][2];
            int row = dk * 16 + l15;
#pragma unroll
            for (int p = 0; p < 4; p++) {
                int ch = (p * 2 + hi) ^ (row & 7);
                uint32_t r0, r1, r2, r3;
                ldsm_x4_t(r0, r1, r2, r3, Vu[buf] + (uint32_t)((row * 8 + ch) * 16));
                vb[2*p][0] = r0; vb[2*p][1] = r1;
                vb[2*p+1][0] = r2; vb[2*p+1][1] = r3;
            }
#pragma unroll
            for (int n = 0; n < 8; n++) mma_16816(o[n], pa[dk], vb[n]);
        }
        __syncthreads();   // all reads of buf done before t+1 overwrites it
    }

    // ---- normalize + write ----
    float inv0 = 1.0f / l0, inv1 = 1.0f / l1;
    int row0 = q0 + w * 16 + (lane >> 2);
    __half* base = ATT + (size_t)(b * Tlen) * Cdim + h * HDim;
#pragma unroll
    for (int n = 0; n < 8; n++) {
        int col = n * 8 + (lane & 3) * 2;
        __half2 h0 = __floats2half2_rn(o[n][0] * inv0, o[n][1] * inv0);
        __half2 h1 = __floats2half2_rn(o[n][2] * inv1, o[n][3] * inv1);
        *reinterpret_cast<__half2*>(base + (size_t)row0 * Cdim + col) = h0;
        *reinterpret_cast<__half2*>(base + (size_t)(row0 + 8) * Cdim + col) = h1;
    }
}

// -------------------------------- launcher ---------------------------------
extern "C" void kernel_launch(void* const* d_in, const int* in_sizes, int n_in,
                              void* d_out, int out_size)
{
    const float* x           = (const float*)d_in[0];
    const float* ln1_g       = (const float*)d_in[1];
    const float* ln1_b       = (const float*)d_in[2];
    const float* w_qkv       = (const float*)d_in[3];
    const float* b_qkv       = (const float*)d_in[4];
    const float* w_attn_proj = (const float*)d_in[5];
    const float* b_attn_proj = (const float*)d_in[6];
    const float* ln2_g       = (const float*)d_in[7];
    const float* ln2_b       = (const float*)d_in[8];
    const float* w_fc        = (const float*)d_in[9];
    const float* b_fc        = (const float*)d_in[10];
    const float* w_mlp_proj  = (const float*)d_in[11];
    const float* b_mlp_proj  = (const float*)d_in[12];
    float* out = (float*)d_out;

    float *X1;
    __half *H16, *QKV16, *ATT16, *FF16, *Wq16, *Wa16, *Wf16, *Wm16;
    cudaGetSymbolAddress((void**)&X1,    g_X1);
    cudaGetSymbolAddress((void**)&H16,   g_H16);
    cudaGetSymbolAddress((void**)&QKV16, g_QKV16);
    cudaGetSymbolAddress((void**)&ATT16, g_ATT16);
    cudaGetSymbolAddress((void**)&FF16,  g_FF16);
    cudaGetSymbolAddress((void**)&Wq16,  g_Wq16);
    cudaGetSymbolAddress((void**)&Wa16,  g_Wa16);
    cudaGetSymbolAddress((void**)&Wf16,  g_Wf16);
    cudaGetSymbolAddress((void**)&Wm16,  g_Wm16);

    cudaFuncSetAttribute(gemm_mma<0,1>, cudaFuncAttributeMaxDynamicSharedMemorySize, GEMM_SMEM);
    cudaFuncSetAttribute(gemm_mma<1,1>, cudaFuncAttributeMaxDynamicSharedMemorySize, GEMM_SMEM);
    cudaFuncSetAttribute(gemm_mma<2,0>, cudaFuncAttributeMaxDynamicSharedMemorySize, GEMM_SMEM);
    cudaFuncSetAttribute(flash_mma, cudaFuncAttributeMaxDynamicSharedMemorySize, FLASH_SMEM);

    cvt_half_kernel<<<(3*Cdim*Cdim/4 + 255)/256, 256>>>(w_qkv, Wq16, 3*Cdim*Cdim/4);
    cvt_half_kernel<<<(Cdim*Cdim/4 + 255)/256, 256>>>(w_attn_proj, Wa16, Cdim*Cdim/4);
    cvt_half_kernel<<<(Cdim*FFdim/4 + 255)/256, 256>>>(w_fc, Wf16, Cdim*FFdim/4);
    cvt_half_kernel<<<(FFdim*Cdim/4 + 255)/256, 256>>>(w_mlp_proj, Wm16, FFdim*Cdim/4);

    // 1. h = LN1(x)                      (fp16 out)
    ln_kernel<<<Mrows / 8, 256>>>(x, ln1_g, ln1_b, H16);
    // 2. qkv = h @ w_qkv + b             (fp16 out)
    gemm_mma<0,1><<<dim3(3 * Cdim / BN, Mrows / BM), 256, GEMM_SMEM>>>(
        H16, Wq16, b_qkv, nullptr, QKV16, Mrows, 3 * Cdim, Cdim);
    // 3. causal flash attention (raw mma) (fp16 out)
    flash_mma<<<dim3(Tlen / 64, Bsz * NHead), 128, FLASH_SMEM>>>(QKV16, ATT16);
    // 4. x1 = x + attn @ w_attn_proj + b (fp32 out)
    gemm_mma<2,0><<<dim3(Cdim / BN, Mrows / BM), 256, GEMM_SMEM>>>(
        ATT16, Wa16, b_attn_proj, x, X1, Mrows, Cdim, Cdim);
    // 5. h = LN2(x1)                     (fp16 out)
    ln_kernel<<<Mrows / 8, 256>>>(X1, ln2_g, ln2_b, H16);
    // 6. ff = gelu(h @ w_fc + b)         (fp16 out)
    gemm_mma<1,1><<<dim3(FFdim / BN, Mrows / BM), 256, GEMM_SMEM>>>(
        H16, Wf16, b_fc, nullptr, FF16, Mrows, FFdim, Cdim);
    // 7. out = x1 + ff @ w_mlp_proj + b  (fp32 out)
    gemm_mma<2,0><<<dim3(Cdim / BN, Mrows / BM), 256, GEMM_SMEM>>>(
        FF16, Wm16, b_mlp_proj, X1, out, Mrows, Cdim, FFdim);
}

// round 10
// speedup vs baseline: 9.4930x; 1.0020x over previous
#include <cuda_runtime.h>
#include <cuda_fp16.h>
#include <math.h>
#include <stdint.h>

// ---------------------------------------------------------------------------
// TransformerBlock B=4,T=2048,C=1024,NH=16,HD=64,FF=4096 fp32.
// R9: 3-stage single-sync GEMM mainloop; 128-row flash blocks; merged cvt.
// ---------------------------------------------------------------------------

#define Bsz   4
#define Tlen  2048
#define Cdim  1024
#define NHead 16
#define HDim  64
#define FFdim 4096
#define Mrows (Bsz * Tlen)   // 8192

// ------------------------- scratch (device globals) ------------------------
__device__ float  g_X1 [Mrows * Cdim];
__device__ __half g_H16  [Mrows * Cdim];
__device__ __half g_QKV16[Mrows * 3 * Cdim];
__device__ __half g_ATT16[Mrows * Cdim];
__device__ __half g_FF16 [Mrows * FFdim];
__device__ __half g_Wq16[Cdim * 3 * Cdim];
__device__ __half g_Wa16[Cdim * Cdim];
__device__ __half g_Wf16[Cdim * FFdim];
__device__ __half g_Wm16[FFdim * Cdim];

// --------------------- fused fp32 -> fp16 weight convert -------------------
__global__ void __launch_bounds__(256)
cvt_all_kernel(const float* __restrict__ wq, const float* __restrict__ wa,
               const float* __restrict__ wf, const float* __restrict__ wm,
               __half* __restrict__ oq, __half* __restrict__ oa,
               __half* __restrict__ of, __half* __restrict__ om)
{
    const int n1 = 3 * Cdim * Cdim / 4;
    const int n2 = Cdim * Cdim / 4;
    const int n3 = Cdim * FFdim / 4;
    int i = blockIdx.x * 256 + threadIdx.x;
    const float* src; __half* dst; int j = i;
    if (j < n1)            { src = wq; dst = oq; }
    else { j -= n1;
    if (j < n2)            { src = wa; dst = oa; }
    else { j -= n2;
    if (j < n3)            { src = wf; dst = of; }
    else { j -= n3;          src = wm; dst = om; } } }
    float4 v = reinterpret_cast<const float4*>(src)[j];
    __half2 h0 = __floats2half2_rn(v.x, v.y);
    __half2 h1 = __floats2half2_rn(v.z, v.w);
    uint2 o = { *(uint32_t*)&h0, *(uint32_t*)&h1 };
    reinterpret_cast<uint2*>(dst)[j] = o;
}

// ------------------------ LayerNorm (warp per row) -------------------------
__global__ void __launch_bounds__(256)
ln_kernel(const float* __restrict__ X, const float* __restrict__ g,
          const float* __restrict__ b, __half* __restrict__ Y)
{
    int w    = threadIdx.x >> 5;
    int lane = threadIdx.x & 31;
    int row  = blockIdx.x * 8 + w;

    const float4* xr = reinterpret_cast<const float4*>(X + (size_t)row * Cdim);
    float4 v[8];
    float sum = 0.0f, sq = 0.0f;
#pragma unroll
    for (int i = 0; i < 8; i++) {
        v[i] = xr[lane + 32 * i];
        sum += v[i].x + v[i].y + v[i].z + v[i].w;
        sq  += v[i].x*v[i].x + v[i].y*v[i].y + v[i].z*v[i].z + v[i].w*v[i].w;
    }
#pragma unroll
    for (int st = 16; st > 0; st >>= 1) {
        sum += __shfl_xor_sync(0xFFFFFFFFu, sum, st);
        sq  += __shfl_xor_sync(0xFFFFFFFFu, sq,  st);
    }
    float mu   = sum * (1.0f / Cdim);
    float var  = sq  * (1.0f / Cdim) - mu * mu;
    float rstd = rsqrtf(var + 1e-5f);

    const float4* gr = reinterpret_cast<const float4*>(g);
    const float4* br = reinterpret_cast<const float4*>(b);
    uint2* yr = reinterpret_cast<uint2*>(Y + (size_t)row * Cdim);
#pragma unroll
    for (int i = 0; i < 8; i++) {
        float4 gg = gr[lane + 32 * i];
        float4 bb = br[lane + 32 * i];
        __half2 h0 = __floats2half2_rn((v[i].x - mu) * rstd * gg.x + bb.x,
                                       (v[i].y - mu) * rstd * gg.y + bb.y);
        __half2 h1 = __floats2half2_rn((v[i].z - mu) * rstd * gg.z + bb.z,
                                       (v[i].w - mu) * rstd * gg.w + bb.w);
        uint2 o = { *(uint32_t*)&h0, *(uint32_t*)&h1 };
        yr[lane + 32 * i] = o;
    }
}

// ------------------------------ common helpers -----------------------------
__device__ __forceinline__ float gelu_f(float x)
{
    float x3 = x * x * x;
    float t  = tanhf(0.7978845608028654f * (x + 0.044715f * x3));
    return 0.5f * x * (1.0f + t);
}

#define CP_ASYNC16(dst, src) \
    asm volatile("cp.async.cg.shared.global [%0], [%1], 16;" :: "r"(dst), "l"(src))
#define CP_COMMIT()   asm volatile("cp.async.commit_group;" ::: "memory")
#define CP_WAIT(n)    asm volatile("cp.async.wait_group %0;" :: "n"(n) : "memory")

__device__ __forceinline__ uint32_t smem_u32(const void* p) {
    uint32_t a;
    asm("{ .reg .u64 t; cvta.to.shared.u64 t, %1; cvt.u32.u64 %0, t; }"
        : "=r"(a) : "l"(p));
    return a;
}

__device__ __forceinline__ void ldsm_x4(uint32_t& r0, uint32_t& r1,
                                        uint32_t& r2, uint32_t& r3, uint32_t addr)
{
    asm volatile("ldmatrix.sync.aligned.m8n8.x4.shared.b16 {%0,%1,%2,%3}, [%4];"
        : "=r"(r0), "=r"(r1), "=r"(r2), "=r"(r3) : "r"(addr));
}
__device__ __forceinline__ void ldsm_x4_t(uint32_t& r0, uint32_t& r1,
                                          uint32_t& r2, uint32_t& r3, uint32_t addr)
{
    asm volatile("ldmatrix.sync.aligned.m8n8.x4.trans.shared.b16 {%0,%1,%2,%3}, [%4];"
        : "=r"(r0), "=r"(r1), "=r"(r2), "=r"(r3) : "r"(addr));
}
__device__ __forceinline__ void mma_16816(float* c, const uint32_t* a,
                                          const uint32_t* b)
{
    asm volatile("mma.sync.aligned.m16n8k16.row.col.f32.f16.f16.f32 "
        "{%0,%1,%2,%3}, {%4,%5,%6,%7}, {%8,%9}, {%0,%1,%2,%3};"
        : "+f"(c[0]), "+f"(c[1]), "+f"(c[2]), "+f"(c[3])
        : "r"(a[0]), "r"(a[1]), "r"(a[2]), "r"(a[3]), "r"(b[0]), "r"(b[1]));
}

// --------------------- raw mma.sync GEMM (3-stage ring) --------------------
static constexpr int BM = 128, BN = 128, BK = 64;
static constexpr int A_BYTES = BM * BK * 2;        // 16384
static constexpr int B_BYTES = BK * BN * 2;        // 16384
static constexpr int STAGE   = A_BYTES + B_BYTES;  // 32768
static constexpr int NSTG    = 3;
static constexpr int GEMM_SMEM = NSTG * STAGE;     // 98304

template<int EPI, int OUTH>
__global__ void __launch_bounds__(256, 2)
gemm_mma(const __half* __restrict__ A, const __half* __restrict__ W,
         const float* __restrict__ bias, const float* __restrict__ R,
         void* __restrict__ Cout, int M, int N, int K)
{
    extern __shared__ __align__(128) char smem[];
    uint32_t sA_u[NSTG], sB_u[NSTG];
#pragma unroll
    for (int i = 0; i < NSTG; i++) {
        sA_u[i] = smem_u32(smem + i * STAGE);
        sB_u[i] = smem_u32(smem + i * STAGE + A_BYTES);
    }

    int tid  = threadIdx.x;
    int wid  = tid >> 5;
    int lane = tid & 31;
    int wm   = wid >> 2;
    int wn   = wid & 3;
    int m0   = blockIdx.y * BM;
    int n0   = blockIdx.x * BN;

    float acc[4][4][4];
#pragma unroll
    for (int i = 0; i < 4; i++)
#pragma unroll
        for (int j = 0; j < 4; j++)
#pragma unroll
            for (int r = 0; r < 4; r++) acc[i][j][r] = 0.0f;

    int nk = K / BK;

    auto issue_stage = [&](int s, int buf) {
        const __half* Ab = A + (size_t)m0 * K + s * BK;
        const __half* Wb = W + (size_t)s * BK * N + n0;
#pragma unroll
        for (int i = 0; i < 4; i++) {
            int f = tid + i * 256;
            int ra = f >> 3, ca = f & 7;
            uint32_t da = sA_u[buf] + (uint32_t)((ra * 8 + (ca ^ (ra & 7))) * 16);
            CP_ASYNC16(da, Ab + (size_t)ra * K + ca * 8);
            int rb = f >> 4, cb = f & 15;
            int pb = (cb & 8) | ((cb & 7) ^ (rb & 7));
            uint32_t db = sB_u[buf] + (uint32_t)((rb * 16 + pb) * 16);
            CP_ASYNC16(db, Wb + (size_t)rb * N + cb * 8);
        }
        CP_COMMIT();
    };

    issue_stage(0, 0);
    issue_stage(1, 1);

    int l15 = lane & 15;
    int hi  = lane >> 4;
    int x   = lane & 7;

    for (int s = 0; s < nk; ++s) {
        int buf = s % NSTG;
        if (s + 1 < nk) { CP_WAIT(1); } else { CP_WAIT(0); }
        __syncthreads();
        if (s + 2 < nk) issue_stage(s + 2, (s + 2) % NSTG);

        uint32_t aT = sA_u[buf];
        uint32_t bT = sB_u[buf];
#pragma unroll
        for (int ks = 0; ks < 4; ++ks) {
            uint32_t a[4][4];
#pragma unroll
            for (int mi = 0; mi < 4; mi++) {
                int row = wm * 64 + mi * 16 + l15;
                int ch  = (ks * 2 + hi) ^ x;
                ldsm_x4(a[mi][0], a[mi][1], a[mi][2], a[mi][3],
                        aT + (uint32_t)((row * 8 + ch) * 16));
            }
            uint32_t b[4][2];
#pragma unroll
            for (int nj = 0; nj < 2; nj++) {
                int row = ks * 16 + l15;
                int cl  = wn * 4 + nj * 2 + hi;
                int ch  = (cl & 8) | ((cl & 7) ^ x);
                uint32_t r0, r1, r2, r3;
                ldsm_x4_t(r0, r1, r2, r3, bT + (uint32_t)((row * 16 + ch) * 16));
                b[nj * 2][0] = r0; b[nj * 2][1] = r1;
                b[nj * 2 + 1][0] = r2; b[nj * 2 + 1][1] = r3;
            }
#pragma unroll
            for (int mi = 0; mi < 4; mi++)
#pragma unroll
                for (int ni = 0; ni < 4; ni++)
                    mma_16816(acc[mi][ni], a[mi], b[ni]);
        }
    }

    int rbase = m0 + wm * 64 + (lane >> 2);
    int cbase = n0 + wn * 32 + (lane & 3) * 2;
#pragma unroll
    for (int mi = 0; mi < 4; mi++) {
#pragma unroll
        for (int ni = 0; ni < 4; ni++) {
            int col = cbase + ni * 8;
            float2 bi = *reinterpret_cast<const float2*>(bias + col);
#pragma unroll
            for (int h = 0; h < 2; h++) {
                int row = rbase + mi * 16 + h * 8;
                float v0 = acc[mi][ni][h * 2 + 0] + bi.x;
                float v1 = acc[mi][ni][h * 2 + 1] + bi.y;
                if (EPI == 1) { v0 = gelu_f(v0); v1 = gelu_f(v1); }
                if (EPI == 2) {
                    float2 rr = *reinterpret_cast<const float2*>(
                        R + (size_t)row * N + col);
                    v0 += rr.x; v1 += rr.y;
                }
                if (OUTH) {
                    __half2 hv = __floats2half2_rn(v0, v1);
                    *reinterpret_cast<__half2*>(
                        (__half*)Cout + (size_t)row * N + col) = hv;
                } else {
                    float2 fv = { v0, v1 };
                    *reinterpret_cast<float2*>(
                        (float*)Cout + (size_t)row * N + col) = fv;
                }
            }
        }
    }
}

// ---------------- raw mma.sync register-resident flash attention -----------
// 256 threads (8 warps), 128 q rows/block (16 per warp), KV tiles 64,
// double-buffered. Q/K/V in swizzled smem; S, P, O, softmax state in regs.
static constexpr int FLASH_SMEM = 16384 + 4 * 8192;   // Q(128x64) + 2*(K,V)

__global__ void __launch_bounds__(256, 2)
flash_mma(const __half* __restrict__ QKV, __half* __restrict__ ATT)
{
    extern __shared__ __align__(128) char smem[];
    uint32_t Qu = smem_u32(smem);
    uint32_t Ku[2] = { Qu + 16384, Qu + 32768 };
    uint32_t Vu[2] = { Qu + 24576, Qu + 40960 };

    int tid  = threadIdx.x;
    int w    = tid >> 5;
    int lane = tid & 31;
    int qt   = gridDim.x - 1 - blockIdx.x;      // heavy tiles first
    int bh   = blockIdx.y;
    int b    = bh >> 4;
    int h    = bh & 15;
    int q0   = qt * 128;

    // 64x64 K/V tile loader (src row stride 3C), swizzled dst; 2 chunks/thread
    auto ld_tile = [&](uint32_t dstu, const __half* src) {
#pragma unroll
        for (int i = 0; i < 2; i++) {
            int f = tid + i * 256;
            int r = f >> 3, c = f & 7;
            uint32_t d = dstu + (uint32_t)((r * 8 + (c ^ (r & 7))) * 16);
            CP_ASYNC16(d, src + (size_t)r * (3 * Cdim) + c * 8);
        }
    };

    const __half* Qg  = QKV + (size_t)(b * Tlen + q0) * (3 * Cdim) + h * HDim;
    const __half* Kg0 = QKV + (size_t)(b * Tlen) * (3 * Cdim) + Cdim + h * HDim;
    // Q: 128 rows x 8 chunks = 1024 chunks, 4/thread
#pragma unroll
    for (int i = 0; i < 4; i++) {
        int f = tid + i * 256;
        int r = f >> 3, c = f & 7;
        uint32_t d = Qu + (uint32_t)((r * 8 + (c ^ (r & 7))) * 16);
        CP_ASYNC16(d, Qg + (size_t)r * (3 * Cdim) + c * 8);
    }
    CP_COMMIT();
    ld_tile(Ku[0], Kg0);
    ld_tile(Vu[0], Kg0 + Cdim);
    CP_COMMIT();

    // Q fragments (A-layout), scaled by 1/sqrt(64)
    uint32_t qa[4][4];
    {
        CP_WAIT(1);
        __syncthreads();
        int l15 = lane & 15, hi = lane >> 4;
        int row = w * 16 + l15;
#pragma unroll
        for (int dk = 0; dk < 4; dk++) {
            int ch = (dk * 2 + hi) ^ (row & 7);
            ldsm_x4(qa[dk][0], qa[dk][1], qa[dk][2], qa[dk][3],
                    Qu + (uint32_t)((row * 8 + ch) * 16));
        }
        __half2 sc = __floats2half2_rn(0.125f, 0.125f);
#pragma unroll
        for (int dk = 0; dk < 4; dk++)
#pragma unroll
            for (int r = 0; r < 4; r++) {
                __half2 v = *reinterpret_cast<__half2*>(&qa[dk][r]);
                v = __hmul2(v, sc);
                qa[dk][r] = *reinterpret_cast<uint32_t*>(&v);
            }
    }

    float o[8][4];
#pragma unroll
    for (int n = 0; n < 8; n++)
#pragma unroll
        for (int r = 0; r < 4; r++) o[n][r] = 0.0f;
    float m0 = -1e30f, m1 = -1e30f, l0 = 0.0f, l1 = 0.0f;

    int g    = lane >> 3;
    int r8   = lane & 7;
    int l15  = lane & 15;
    int hi   = lane >> 4;
    int qr   = q0 + w * 16 + (lane >> 2);   // row for c0/c1; +8 for c2/c3
    int ntm1 = q0 >> 6;                     // first tile needing a mask
    int nt   = ntm1 + 1;                    // last tile index

    for (int t = 0; t <= nt; ++t) {
        int buf = t & 1;
        if (t < nt) {
            const __half* Kg = QKV + (size_t)(b * Tlen + (t + 1) * 64) * (3 * Cdim)
                             + Cdim + h * HDim;
            ld_tile(Ku[buf ^ 1], Kg);
            ld_tile(Vu[buf ^ 1], Kg + Cdim);
            CP_COMMIT();
            CP_WAIT(1);
        } else {
            CP_WAIT(0);
        }
        __syncthreads();

        // ---- S = Q @ K^T ----
        float s[8][4];
#pragma unroll
        for (int n = 0; n < 8; n++)
#pragma unroll
            for (int r = 0; r < 4; r++) s[n][r] = 0.0f;
#pragma unroll
        for (int dk = 0; dk < 4; dk++) {
            uint32_t kb[8][2];
#pragma unroll
            for (int p = 0; p < 4; p++) {
                int row = p * 16 + (g >> 1) * 8 + r8;
                int ch  = (dk * 2 + (g & 1)) ^ (row & 7);
                uint32_t r0, r1, r2, r3;
                ldsm_x4(r0, r1, r2, r3, Ku[buf] + (uint32_t)((row * 8 + ch) * 16));
                kb[2*p][0] = r0; kb[2*p][1] = r1;
                kb[2*p+1][0] = r2; kb[2*p+1][1] = r3;
            }
#pragma unroll
            for (int n = 0; n < 8; n++) mma_16816(s[n], qa[dk], kb[n]);
        }

        // ---- online softmax in registers ----
        bool needmask = (t >= ntm1);
        float mx0 = -1e30f, mx1 = -1e30f;
#pragma unroll
        for (int n = 0; n < 8; n++) {
            if (needmask) {
                int col = t * 64 + n * 8 + (lane & 3) * 2;
                if (col     > qr)     s[n][0] = -1e30f;
                if (col + 1 > qr)     s[n][1] = -1e30f;
                if (col     > qr + 8) s[n][2] = -1e30f;
                if (col + 1 > qr + 8) s[n][3] = -1e30f;
            }
            mx0 = fmaxf(mx0, fmaxf(s[n][0], s[n][1]));
            mx1 = fmaxf(mx1, fmaxf(s[n][2], s[n][3]));
        }
        mx0 = fmaxf(mx0, __shfl_xor_sync(0xFFFFFFFFu, mx0, 1));
        mx0 = fmaxf(mx0, __shfl_xor_sync(0xFFFFFFFFu, mx0, 2));
        mx1 = fmaxf(mx1, __shfl_xor_sync(0xFFFFFFFFu, mx1, 1));
        mx1 = fmaxf(mx1, __shfl_xor_sync(0xFFFFFFFFu, mx1, 2));

        float mn0 = fmaxf(m0, mx0), mn1 = fmaxf(m1, mx1);
        float sc0 = __expf(m0 - mn0), sc1 = __expf(m1 - mn1);
        float sum0 = 0.0f, sum1 = 0.0f;
        uint32_t pa[4][4];
#pragma unroll
        for (int dk = 0; dk < 4; dk++) {
            float e00 = __expf(s[2*dk][0]   - mn0);
            float e01 = __expf(s[2*dk][1]   - mn0);
            float e02 = __expf(s[2*dk][2]   - mn1);
            float e03 = __expf(s[2*dk][3]   - mn1);
            float e10 = __expf(s[2*dk+1][0] - mn0);
            float e11 = __expf(s[2*dk+1][1] - mn0);
            float e12 = __expf(s[2*dk+1][2] - mn1);
            float e13 = __expf(s[2*dk+1][3] - mn1);
            sum0 += e00 + e01 + e10 + e11;
            sum1 += e02 + e03 + e12 + e13;
            __half2 h0 = __floats2half2_rn(e00, e01);
            __half2 h1 = __floats2half2_rn(e02, e03);
            __half2 h2 = __floats2half2_rn(e10, e11);
            __half2 h3 = __floats2half2_rn(e12, e13);
            pa[dk][0] = *reinterpret_cast<uint32_t*>(&h0);
            pa[dk][1] = *reinterpret_cast<uint32_t*>(&h1);
            pa[dk][2] = *reinterpret_cast<uint32_t*>(&h2);
            pa[dk][3] = *reinterpret_cast<uint32_t*>(&h3);
        }
        sum0 += __shfl_xor_sync(0xFFFFFFFFu, sum0, 1);
        sum0 += __shfl_xor_sync(0xFFFFFFFFu, sum0, 2);
        sum1 += __shfl_xor_sync(0xFFFFFFFFu, sum1, 1);
        sum1 += __shfl_xor_sync(0xFFFFFFFFu, sum1, 2);
        l0 = l0 * sc0 + sum0;
        l1 = l1 * sc1 + sum1;
        m0 = mn0; m1 = mn1;
#pragma unroll
        for (int n = 0; n < 8; n++) {
            o[n][0] *= sc0; o[n][1] *= sc0;
            o[n][2] *= sc1; o[n][3] *= sc1;
        }

        // ---- O += P @ V ----
#pragma unroll
        for (int dk = 0; dk < 4; dk++) {
            uint32_t vb[8][2];
            int row = dk * 16 + l15;
#pragma unroll
            for (int p = 0; p < 4; p++) {
                int ch = (p * 2 + hi) ^ (row & 7);
                uint32_t r0, r1, r2, r3;
                ldsm_x4_t(r0, r1, r2, r3, Vu[buf] + (uint32_t)((row * 8 + ch) * 16));
                vb[2*p][0] = r0; vb[2*p][1] = r1;
                vb[2*p+1][0] = r2; vb[2*p+1][1] = r3;
            }
#pragma unroll
            for (int n = 0; n < 8; n++) mma_16816(o[n], pa[dk], vb[n]);
        }
        __syncthreads();
    }

    // ---- normalize + write ----
    float inv0 = 1.0f / l0, inv1 = 1.0f / l1;
    int row0 = q0 + w * 16 + (lane >> 2);
    __half* base = ATT + (size_t)(b * Tlen) * Cdim + h * HDim;
#pragma unroll
    for (int n = 0; n < 8; n++) {
        int col = n * 8 + (lane & 3) * 2;
        __half2 h0 = __floats2half2_rn(o[n][0] * inv0, o[n][1] * inv0);
        __half2 h1 = __floats2half2_rn(o[n][2] * inv1, o[n][3] * inv1);
        *reinterpret_cast<__half2*>(base + (size_t)row0 * Cdim + col) = h0;
        *reinterpret_cast<__half2*>(base + (size_t)(row0 + 8) * Cdim + col) = h1;
    }
}

// -------------------------------- launcher ---------------------------------
extern "C" void kernel_launch(void* const* d_in, const int* in_sizes, int n_in,
                              void* d_out, int out_size)
{
    const float* x           = (const float*)d_in[0];
    const float* ln1_g       = (const float*)d_in[1];
    const float* ln1_b       = (const float*)d_in[2];
    const float* w_qkv       = (const float*)d_in[3];
    const float* b_qkv       = (const float*)d_in[4];
    const float* w_attn_proj = (const float*)d_in[5];
    const float* b_attn_proj = (const float*)d_in[6];
    const float* ln2_g       = (const float*)d_in[7];
    const float* ln2_b       = (const float*)d_in[8];
    const float* w_fc        = (const float*)d_in[9];
    const float* b_fc        = (const float*)d_in[10];
    const float* w_mlp_proj  = (const float*)d_in[11];
    const float* b_mlp_proj  = (const float*)d_in[12];
    float* out = (float*)d_out;

    float *X1;
    __half *H16, *QKV16, *ATT16, *FF16, *Wq16, *Wa16, *Wf16, *Wm16;
    cudaGetSymbolAddress((void**)&X1,    g_X1);
    cudaGetSymbolAddress((void**)&H16,   g_H16);
    cudaGetSymbolAddress((void**)&QKV16, g_QKV16);
    cudaGetSymbolAddress((void**)&ATT16, g_ATT16);
    cudaGetSymbolAddress((void**)&FF16,  g_FF16);
    cudaGetSymbolAddress((void**)&Wq16,  g_Wq16);
    cudaGetSymbolAddress((void**)&Wa16,  g_Wa16);
    cudaGetSymbolAddress((void**)&Wf16,  g_Wf16);
    cudaGetSymbolAddress((void**)&Wm16,  g_Wm16);

    cudaFuncSetAttribute(gemm_mma<0,1>, cudaFuncAttributeMaxDynamicSharedMemorySize, GEMM_SMEM);
    cudaFuncSetAttribute(gemm_mma<1,1>, cudaFuncAttributeMaxDynamicSharedMemorySize, GEMM_SMEM);
    cudaFuncSetAttribute(gemm_mma<2,0>, cudaFuncAttributeMaxDynamicSharedMemorySize, GEMM_SMEM);
    cudaFuncSetAttribute(flash_mma, cudaFuncAttributeMaxDynamicSharedMemorySize, FLASH_SMEM);

    // weight conversion (single launch)
    {
        int total4 = (3 * Cdim * Cdim + Cdim * Cdim + Cdim * FFdim + FFdim * Cdim) / 4;
        cvt_all_kernel<<<(total4 + 255) / 256, 256>>>(
            w_qkv, w_attn_proj, w_fc, w_mlp_proj, Wq16, Wa16, Wf16, Wm16);
    }

    // 1. h = LN1(x)                      (fp16 out)
    ln_kernel<<<Mrows / 8, 256>>>(x, ln1_g, ln1_b, H16);
    // 2. qkv = h @ w_qkv + b             (fp16 out)
    gemm_mma<0,1><<<dim3(3 * Cdim / BN, Mrows / BM), 256, GEMM_SMEM>>>(
        H16, Wq16, b_qkv, nullptr, QKV16, Mrows, 3 * Cdim, Cdim);
    // 3. causal flash attention (raw mma) (fp16 out)
    flash_mma<<<dim3(Tlen / 128, Bsz * NHead), 256, FLASH_SMEM>>>(QKV16, ATT16);
    // 4. x1 = x + attn @ w_attn_proj + b (fp32 out)
    gemm_mma<2,0><<<dim3(Cdim / BN, Mrows / BM), 256, GEMM_SMEM>>>(
        ATT16, Wa16, b_attn_proj, x, X1, Mrows, Cdim, Cdim);
    // 5. h = LN2(x1)                     (fp16 out)
    ln_kernel<<<Mrows / 8, 256>>>(X1, ln2_g, ln2_b, H16);
    // 6. ff = gelu(h @ w_fc + b)         (fp16 out)
    gemm_mma<1,1><<<dim3(FFdim / BN, Mrows / BM), 256, GEMM_SMEM>>>(
        H16, Wf16, b_fc, nullptr, FF16, Mrows, FFdim, Cdim);
    // 7. out = x1 + ff @ w_mlp_proj + b  (fp32 out)
    gemm_mma<2,0><<<dim3(Cdim / BN, Mrows / BM), 256, GEMM_SMEM>>>(
        FF16, Wm16, b_mlp_proj, X1, out, Mrows, Cdim, FFdim);
}